// round 1
// baseline (speedup 1.0000x reference)
#include <cuda_runtime.h>

// Problem constants
#define BB   2
#define TT   4096
#define CC   512
#define HH   8
#define DD   64
#define MTOT (BB*TT)          // 8192
#define QTILES (TT/64)        // 64

// Scratch (device globals: allocation-free rule)
__device__ float g_q[BB*HH*TT*DD];   // [b,h,t,d]
__device__ float g_k[BB*HH*TT*DD];
__device__ float g_v[BB*HH*TT*DD];
__device__ float g_y[BB*TT*CC];      // [b,t,c] attention output

// ---------------------------------------------------------------------------
// GEMM: out[m,n] = sum_k in[m,k]*W[n,k] + b[n]   (x @ W^T + b)
// Tiles: BM=64, BN=64, BK=32. 256 threads, 4x4 microtile.
// Smem layout [k][m] with xor swizzle on 4-float column groups.
// ---------------------------------------------------------------------------

__global__ __launch_bounds__(256, 4) void qkv_kernel(
    const float* __restrict__ x,
    const float* __restrict__ Wq, const float* __restrict__ bq,
    const float* __restrict__ Wk, const float* __restrict__ bk,
    const float* __restrict__ Wv, const float* __restrict__ bv)
{
    __shared__ float As[32*64];   // [k][m], swizzled
    __shared__ float Bs[32*64];   // [k][n], swizzled

    const int z = blockIdx.z;
    const float* __restrict__ W    = (z == 0) ? Wq : (z == 1) ? Wk : Wv;
    const float* __restrict__ bias = (z == 0) ? bq : (z == 1) ? bk : bv;
    float* __restrict__ outp       = (z == 0) ? g_q : (z == 1) ? g_k : g_v;

    const int m0 = blockIdx.y * 64;
    const int n0 = blockIdx.x * 64;
    const int tid = threadIdx.x;
    const int tx = tid & 15, ty = tid >> 4;

    float acc[4][4] = {};

    for (int k0 = 0; k0 < CC; k0 += 32) {
        #pragma unroll
        for (int l = 0; l < 2; l++) {
            int idx = tid + l * 256;        // 0..511
            int row = idx >> 3;             // 0..63  (m or n)
            int kc  = (idx & 7) << 2;       // 0..28 step 4 (k)
            int cg  = ((row >> 2) ^ (kc >> 2)) & 15;
            int ml  = row & 3;

            float4 a = *(const float4*)(x + (m0 + row) * CC + k0 + kc);
            float* pa = As + kc * 64 + cg * 4 + ml;
            pa[0] = a.x; pa[64] = a.y; pa[128] = a.z; pa[192] = a.w;

            float4 b = *(const float4*)(W + (n0 + row) * CC + k0 + kc);
            float* pb = Bs + kc * 64 + cg * 4 + ml;
            pb[0] = b.x; pb[64] = b.y; pb[128] = b.z; pb[192] = b.w;
        }
        __syncthreads();

        #pragma unroll
        for (int kk = 0; kk < 32; kk++) {
            float4 a = *(const float4*)(As + kk * 64 + ((ty ^ (kk >> 2)) & 15) * 4);
            float4 b = *(const float4*)(Bs + kk * 64 + ((tx ^ (kk >> 2)) & 15) * 4);
            acc[0][0] += a.x * b.x; acc[0][1] += a.x * b.y; acc[0][2] += a.x * b.z; acc[0][3] += a.x * b.w;
            acc[1][0] += a.y * b.x; acc[1][1] += a.y * b.y; acc[1][2] += a.y * b.z; acc[1][3] += a.y * b.w;
            acc[2][0] += a.z * b.x; acc[2][1] += a.z * b.y; acc[2][2] += a.z * b.z; acc[2][3] += a.z * b.w;
            acc[3][0] += a.w * b.x; acc[3][1] += a.w * b.y; acc[3][2] += a.w * b.z; acc[3][3] += a.w * b.w;
        }
        __syncthreads();
    }

    // Store head-split: out[b,h,t,d], h = n0/64
    const int h = blockIdx.x;
    float4 bv4 = *(const float4*)(bias + n0 + tx * 4);
    #pragma unroll
    for (int i = 0; i < 4; i++) {
        int m = m0 + ty * 4 + i;
        int bidx = m >> 12;        // / 4096
        int t = m & 4095;
        float4 r;
        r.x = acc[i][0] + bv4.x; r.y = acc[i][1] + bv4.y;
        r.z = acc[i][2] + bv4.z; r.w = acc[i][3] + bv4.w;
        *(float4*)(outp + (((bidx * HH + h) * TT + t) << 6) + tx * 4) = r;
    }
}

__global__ __launch_bounds__(256, 4) void proj_kernel(
    const float* __restrict__ Wp, const float* __restrict__ bp,
    float* __restrict__ out)
{
    __shared__ float As[32*64];
    __shared__ float Bs[32*64];

    const int m0 = blockIdx.y * 64;
    const int n0 = blockIdx.x * 64;
    const int tid = threadIdx.x;
    const int tx = tid & 15, ty = tid >> 4;

    float acc[4][4] = {};

    for (int k0 = 0; k0 < CC; k0 += 32) {
        #pragma unroll
        for (int l = 0; l < 2; l++) {
            int idx = tid + l * 256;
            int row = idx >> 3;
            int kc  = (idx & 7) << 2;
            int cg  = ((row >> 2) ^ (kc >> 2)) & 15;
            int ml  = row & 3;

            float4 a = *(const float4*)(g_y + (m0 + row) * CC + k0 + kc);
            float* pa = As + kc * 64 + cg * 4 + ml;
            pa[0] = a.x; pa[64] = a.y; pa[128] = a.z; pa[192] = a.w;

            float4 b = *(const float4*)(Wp + (n0 + row) * CC + k0 + kc);
            float* pb = Bs + kc * 64 + cg * 4 + ml;
            pb[0] = b.x; pb[64] = b.y; pb[128] = b.z; pb[192] = b.w;
        }
        __syncthreads();

        #pragma unroll
        for (int kk = 0; kk < 32; kk++) {
            float4 a = *(const float4*)(As + kk * 64 + ((ty ^ (kk >> 2)) & 15) * 4);
            float4 b = *(const float4*)(Bs + kk * 64 + ((tx ^ (kk >> 2)) & 15) * 4);
            acc[0][0] += a.x * b.x; acc[0][1] += a.x * b.y; acc[0][2] += a.x * b.z; acc[0][3] += a.x * b.w;
            acc[1][0] += a.y * b.x; acc[1][1] += a.y * b.y; acc[1][2] += a.y * b.z; acc[1][3] += a.y * b.w;
            acc[2][0] += a.z * b.x; acc[2][1] += a.z * b.y; acc[2][2] += a.z * b.z; acc[2][3] += a.z * b.w;
            acc[3][0] += a.w * b.x; acc[3][1] += a.w * b.y; acc[3][2] += a.w * b.z; acc[3][3] += a.w * b.w;
        }
        __syncthreads();
    }

    float4 bv4 = *(const float4*)(bp + n0 + tx * 4);
    #pragma unroll
    for (int i = 0; i < 4; i++) {
        int m = m0 + ty * 4 + i;
        float4 r;
        r.x = acc[i][0] + bv4.x; r.y = acc[i][1] + bv4.y;
        r.z = acc[i][2] + bv4.z; r.w = acc[i][3] + bv4.w;
        *(float4*)(out + m * CC + n0 + tx * 4) = r;
    }
}

// ---------------------------------------------------------------------------
// Flash attention (fp32). One block = (bh, q-tile of 64 rows). 256 threads.
// Smem: Qs (swizzled), KV (time-shared: K-phase then V-phase), Ps. 48KB total.
// ---------------------------------------------------------------------------

#define NEG_INF (-1e30f)

__global__ __launch_bounds__(256, 2) void attn_kernel()
{
    __shared__ float Qs[64*64];
    __shared__ float KV[64*64];
    __shared__ float Ps[64*64];

    const int qt = (QTILES - 1) - blockIdx.x;   // big tiles first
    const int bh = blockIdx.y;
    const float* __restrict__ Qp = g_q + bh * (TT * DD);
    const float* __restrict__ Kp = g_k + bh * (TT * DD);
    const float* __restrict__ Vp = g_v + bh * (TT * DD);

    const int tid = threadIdx.x;
    const int tx = tid & 15, ty = tid >> 4;
    const int q0 = qt << 6;
    const float scale = 0.125f;   // 1/sqrt(64)

    // Load Q tile (scaled), row-major with column-group swizzle
    #pragma unroll
    for (int l = 0; l < 4; l++) {
        int idx = tid + l * 256;
        int row = idx >> 4;
        int dg  = idx & 15;
        float4 v = *(const float4*)(Qp + ((q0 + row) << 6) + dg * 4);
        v.x *= scale; v.y *= scale; v.z *= scale; v.w *= scale;
        *(float4*)(Qs + row * 64 + ((dg ^ (row >> 2)) & 15) * 4) = v;
    }

    float m_i[4], l_i[4], o[4][4] = {};
    #pragma unroll
    for (int i = 0; i < 4; i++) { m_i[i] = NEG_INF; l_i[i] = 0.f; }

    for (int kt = 0; kt <= qt; kt++) {
        const int k0 = kt << 6;

        // Load K tile -> smem, prefetch V tile -> regs
        float4 vreg[4];
        #pragma unroll
        for (int l = 0; l < 4; l++) {
            int idx = tid + l * 256;
            int row = idx >> 4;
            int dg  = idx & 15;
            float4 kv = *(const float4*)(Kp + ((k0 + row) << 6) + dg * 4);
            *(float4*)(KV + row * 64 + ((dg ^ (row >> 2)) & 15) * 4) = kv;
            vreg[l] = *(const float4*)(Vp + ((k0 + row) << 6) + dg * 4);
        }
        __syncthreads();   // KV(K) + Qs ready

        // S = Q K^T  (4x4 microtile per thread)
        float s[4][4] = {};
        #pragma unroll
        for (int dg = 0; dg < 16; dg++) {
            float4 q4[4], k4[4];
            #pragma unroll
            for (int i = 0; i < 4; i++)
                q4[i] = *(const float4*)(Qs + (ty * 4 + i) * 64 + ((dg ^ ty) & 15) * 4);
            #pragma unroll
            for (int j = 0; j < 4; j++)
                k4[j] = *(const float4*)(KV + (tx * 4 + j) * 64 + ((dg ^ tx) & 15) * 4);
            #pragma unroll
            for (int i = 0; i < 4; i++)
                #pragma unroll
                for (int j = 0; j < 4; j++)
                    s[i][j] += q4[i].x * k4[j].x + q4[i].y * k4[j].y
                             + q4[i].z * k4[j].z + q4[i].w * k4[j].w;
        }

        // Causal mask on the diagonal tile (k0 == q0)
        if (kt == qt) {
            #pragma unroll
            for (int i = 0; i < 4; i++)
                #pragma unroll
                for (int j = 0; j < 4; j++)
                    if (tx * 4 + j > ty * 4 + i) s[i][j] = NEG_INF;
        }

        // Online softmax: row reduce across the 16 tx-threads (intra half-warp)
        #pragma unroll
        for (int i = 0; i < 4; i++) {
            float mx = fmaxf(fmaxf(s[i][0], s[i][1]), fmaxf(s[i][2], s[i][3]));
            #pragma unroll
            for (int off = 8; off > 0; off >>= 1)
                mx = fmaxf(mx, __shfl_xor_sync(0xffffffffu, mx, off));
            float mnew = fmaxf(m_i[i], mx);
            float corr = __expf(m_i[i] - mnew);
            float sum = 0.f;
            #pragma unroll
            for (int j = 0; j < 4; j++) { s[i][j] = __expf(s[i][j] - mnew); sum += s[i][j]; }
            #pragma unroll
            for (int off = 8; off > 0; off >>= 1)
                sum += __shfl_xor_sync(0xffffffffu, sum, off);
            l_i[i] = l_i[i] * corr + sum;
            m_i[i] = mnew;
            o[i][0] *= corr; o[i][1] *= corr; o[i][2] *= corr; o[i][3] *= corr;
        }
        __syncthreads();   // done reading KV(K)

        // Store V (regs -> KV buffer) and P
        #pragma unroll
        for (int l = 0; l < 4; l++) {
            int idx = tid + l * 256;
            int row = idx >> 4;
            int dg  = idx & 15;
            *(float4*)(KV + row * 64 + ((dg ^ (row >> 2)) & 15) * 4) = vreg[l];
        }
        #pragma unroll
        for (int i = 0; i < 4; i++)
            *(float4*)(Ps + (ty * 4 + i) * 64 + tx * 4) =
                make_float4(s[i][0], s[i][1], s[i][2], s[i][3]);
        __syncthreads();   // KV(V) + Ps ready

        // O += P V
        #pragma unroll
        for (int kb = 0; kb < 16; kb++) {
            float4 pr[4];
            #pragma unroll
            for (int i = 0; i < 4; i++)
                pr[i] = *(const float4*)(Ps + (ty * 4 + i) * 64 + kb * 4);
            #pragma unroll
            for (int u = 0; u < 4; u++) {
                int key = kb * 4 + u;
                float4 vv = *(const float4*)(KV + key * 64 + ((tx ^ (key >> 2)) & 15) * 4);
                #pragma unroll
                for (int i = 0; i < 4; i++) {
                    float pe = (u == 0) ? pr[i].x : (u == 1) ? pr[i].y
                             : (u == 2) ? pr[i].z : pr[i].w;
                    o[i][0] += pe * vv.x; o[i][1] += pe * vv.y;
                    o[i][2] += pe * vv.z; o[i][3] += pe * vv.w;
                }
            }
        }
        __syncthreads();   // done reading KV(V)/Ps before next tile overwrites
    }

    // Epilogue: normalize and write y[b, t, h*64 + d]
    const int b = bh >> 3, h = bh & 7;
    #pragma unroll
    for (int i = 0; i < 4; i++) {
        float inv = 1.0f / l_i[i];
        int t = q0 + ty * 4 + i;
        float4 r = make_float4(o[i][0] * inv, o[i][1] * inv,
                               o[i][2] * inv, o[i][3] * inv);
        *(float4*)(g_y + (b * TT + t) * CC + h * DD + tx * 4) = r;
    }
}

// ---------------------------------------------------------------------------
// Launch: inputs (metadata order): x, weight, state, Wq, bq, Wk, bk, Wv, bv, Wp, bp
// ---------------------------------------------------------------------------
extern "C" void kernel_launch(void* const* d_in, const int* in_sizes, int n_in,
                              void* d_out, int out_size)
{
    (void)in_sizes; (void)n_in; (void)out_size;
    const float* x  = (const float*)d_in[0];
    const float* Wq = (const float*)d_in[3];
    const float* bq = (const float*)d_in[4];
    const float* Wk = (const float*)d_in[5];
    const float* bk = (const float*)d_in[6];
    const float* Wv = (const float*)d_in[7];
    const float* bv = (const float*)d_in[8];
    const float* Wp = (const float*)d_in[9];
    const float* bp = (const float*)d_in[10];
    float* out = (float*)d_out;

    dim3 gqkv(CC / 64, MTOT / 64, 3);      // (8, 128, 3)
    qkv_kernel<<<gqkv, 256>>>(x, Wq, bq, Wk, bk, Wv, bv);

    dim3 gattn(QTILES, BB * HH);           // (64, 16)
    attn_kernel<<<gattn, 256>>>();

    dim3 gproj(CC / 64, MTOT / 64);        // (8, 128)
    proj_kernel<<<gproj, 256>>>(Wp, bp, out);
}

// round 3
// speedup vs baseline: 2.7572x; 2.7572x over previous
#include <cuda_runtime.h>
#include <cstdint>

#define BBATCH 2
#define TSEQ   4096
#define CDIM   512
#define NHEAD  8
#define HDIM   64
#define MROWS  (BBATCH*TSEQ)

// Internal scratch (device globals: allocation-free rule)
__device__ float g_q[BBATCH*NHEAD*TSEQ*HDIM];
__device__ float g_k[BBATCH*NHEAD*TSEQ*HDIM];
__device__ float g_v[BBATCH*NHEAD*TSEQ*HDIM];
__device__ float g_y[BBATCH*TSEQ*CDIM];

__device__ __forceinline__ unsigned f2tf(float x){
    unsigned u; asm("cvt.rna.tf32.f32 %0, %1;" : "=r"(u) : "f"(x)); return u;
}

__device__ __forceinline__ void mma_tf32(float c[4],
    unsigned a0, unsigned a1, unsigned a2, unsigned a3,
    unsigned b0, unsigned b1)
{
    asm volatile(
        "mma.sync.aligned.m16n8k8.row.col.f32.tf32.tf32.f32 "
        "{%0,%1,%2,%3}, {%4,%5,%6,%7}, {%8,%9}, {%0,%1,%2,%3};"
        : "+f"(c[0]), "+f"(c[1]), "+f"(c[2]), "+f"(c[3])
        : "r"(a0), "r"(a1), "r"(a2), "r"(a3), "r"(b0), "r"(b1));
}

// ---------------------------------------------------------------------------
// GEMM: out = A @ W^T + bias.  M=8192, N=512, K=512.
// Block tile 128x64, BK=32, 256 threads = 8 warps (4 M x 2 N), warp 32x32.
// Smem padded stride 36 (36%32==4 -> (4g+tig) injective: conflict-free LDS).
// MODE: 0/1/2 -> head-split store to g_q/g_k/g_v; 3 -> A=g_y, row-major out.
// ---------------------------------------------------------------------------
#define GST 36

template<int MODE>
__global__ __launch_bounds__(256,2) void gemm_tf32(
    const float* __restrict__ Ain, const float* __restrict__ W,
    const float* __restrict__ bias, float* __restrict__ outp)
{
    __shared__ unsigned sA[128*GST];
    __shared__ unsigned sB[64*GST];

    const float* __restrict__ A = (MODE == 3) ? (const float*)g_y : Ain;
    float* __restrict__ out =
        (MODE == 0) ? g_q : (MODE == 1) ? g_k : (MODE == 2) ? g_v : outp;

    const int tid = threadIdx.x, lane = tid & 31, warp = tid >> 5;
    const int wm = warp >> 1, wn = warp & 1;
    const int g = lane >> 2, tig = lane & 3;
    const int m0 = blockIdx.y * 128, n0 = blockIdx.x * 64;

    float acc[2][4][4] = {};

    float4 ra[4], rb[2];
    #pragma unroll
    for (int l = 0; l < 4; l++) {
        int idx = tid + l*256;
        ra[l] = *(const float4*)(A + (m0 + (idx>>3))*CDIM + ((idx&7)<<2));
    }
    #pragma unroll
    for (int l = 0; l < 2; l++) {
        int idx = tid + l*256;
        rb[l] = *(const float4*)(W + (n0 + (idx>>3))*CDIM + ((idx&7)<<2));
    }

    for (int it = 0; it < 16; it++) {
        #pragma unroll
        for (int l = 0; l < 4; l++) {
            int idx = tid + l*256; int row = idx>>3, k0 = (idx&7)<<2;
            *(uint4*)&sA[row*GST + k0] =
                make_uint4(f2tf(ra[l].x), f2tf(ra[l].y), f2tf(ra[l].z), f2tf(ra[l].w));
        }
        #pragma unroll
        for (int l = 0; l < 2; l++) {
            int idx = tid + l*256; int row = idx>>3, k0 = (idx&7)<<2;
            *(uint4*)&sB[row*GST + k0] =
                make_uint4(f2tf(rb[l].x), f2tf(rb[l].y), f2tf(rb[l].z), f2tf(rb[l].w));
        }
        __syncthreads();

        if (it < 15) {
            int kb = (it+1) * 32;
            #pragma unroll
            for (int l = 0; l < 4; l++) {
                int idx = tid + l*256;
                ra[l] = *(const float4*)(A + (m0 + (idx>>3))*CDIM + kb + ((idx&7)<<2));
            }
            #pragma unroll
            for (int l = 0; l < 2; l++) {
                int idx = tid + l*256;
                rb[l] = *(const float4*)(W + (n0 + (idx>>3))*CDIM + kb + ((idx&7)<<2));
            }
        }

        #pragma unroll
        for (int ik = 0; ik < 4; ik++) {
            unsigned a[2][4];
            #pragma unroll
            for (int mt = 0; mt < 2; mt++) {
                const unsigned* p = &sA[(wm*32 + mt*16)*GST + ik*8];
                a[mt][0] = p[g*GST + tig];
                a[mt][1] = p[(g+8)*GST + tig];
                a[mt][2] = p[g*GST + tig + 4];
                a[mt][3] = p[(g+8)*GST + tig + 4];
            }
            #pragma unroll
            for (int nt = 0; nt < 4; nt++) {
                const unsigned* p = &sB[(wn*32 + nt*8)*GST + ik*8];
                unsigned b0 = p[g*GST + tig], b1 = p[g*GST + tig + 4];
                mma_tf32(acc[0][nt], a[0][0], a[0][1], a[0][2], a[0][3], b0, b1);
                mma_tf32(acc[1][nt], a[1][0], a[1][1], a[1][2], a[1][3], b0, b1);
            }
        }
        __syncthreads();
    }

    #pragma unroll
    for (int mt = 0; mt < 2; mt++) {
        #pragma unroll
        for (int r = 0; r < 2; r++) {
            int row = m0 + wm*32 + mt*16 + g + r*8;
            #pragma unroll
            for (int nt = 0; nt < 4; nt++) {
                int col = n0 + wn*32 + nt*8 + tig*2;
                float2 bv = *(const float2*)(bias + col);
                float2 o = make_float2(acc[mt][nt][r*2+0] + bv.x,
                                       acc[mt][nt][r*2+1] + bv.y);
                if (MODE < 3) {
                    int b = row >> 12, t = row & 4095, h = col >> 6, d = col & 63;
                    *(float2*)(out + (((b*NHEAD + h)*TSEQ + t) << 6) + d) = o;
                } else {
                    *(float2*)(out + row*CDIM + col) = o;
                }
            }
        }
    }
}

// ---------------------------------------------------------------------------
// Flash attention, tf32 mma. Block = 128 q-rows x (b,h). 8 warps x 16 rows.
// Q held in A-fragments in registers; K/V staged in one padded smem buffer
// (stride 76: 76%32==12 -> both (4g+tig) and (12tig+g) injective mod 32);
// next K/V tile prefetched into registers during compute.
// ---------------------------------------------------------------------------
#define QST 76

__global__ __launch_bounds__(256,1) void attn_tf32()
{
    __shared__ unsigned smem[128*QST];            // 38912 B
    unsigned* Qs = smem;                           // staging only
    unsigned* Ks = smem;                           // [64][76]
    unsigned* Vs = smem + 64*QST;                  // [64][76]

    const int tid = threadIdx.x, lane = tid & 31, warp = tid >> 5;
    const int g = lane >> 2, tig = lane & 3;
    const int qi = (TSEQ/128 - 1) - blockIdx.x;    // big tiles first
    const int bh = blockIdx.y;
    const int q0 = qi * 128;
    const float* __restrict__ Qp = g_q + bh*(TSEQ*HDIM);
    const float* __restrict__ Kp = g_k + bh*(TSEQ*HDIM);
    const float* __restrict__ Vp = g_v + bh*(TSEQ*HDIM);

    // ---- stage Q (scaled), read A-fragments into registers ----
    #pragma unroll
    for (int l = 0; l < 8; l++) {
        int idx = tid + l*256; int row = idx >> 4, fc = idx & 15;
        float4 q = *(const float4*)(Qp + ((q0 + row) << 6) + fc*4);
        *(uint4*)&Qs[row*QST + fc*4] =
            make_uint4(f2tf(q.x*0.125f), f2tf(q.y*0.125f),
                       f2tf(q.z*0.125f), f2tf(q.w*0.125f));
    }
    __syncthreads();
    unsigned qa[8][4];
    #pragma unroll
    for (int ik = 0; ik < 8; ik++) {
        const unsigned* p = &Qs[(warp*16)*QST + ik*8];
        qa[ik][0] = p[g*QST + tig];
        qa[ik][1] = p[(g+8)*QST + tig];
        qa[ik][2] = p[g*QST + tig + 4];
        qa[ik][3] = p[(g+8)*QST + tig + 4];
    }
    __syncthreads();   // all warps done reading Q before K/V overwrite

    const int nk = (q0 >> 6) + 2;

    float4 rk[4], rv[4];
    #pragma unroll
    for (int l = 0; l < 4; l++) {
        int idx = tid + l*256; int row = idx >> 4, fc = idx & 15;
        rk[l] = *(const float4*)(Kp + (row << 6) + fc*4);
        rv[l] = *(const float4*)(Vp + (row << 6) + fc*4);
    }

    float m0r = -1e30f, m1r = -1e30f, l0r = 0.f, l1r = 0.f;
    float O[8][4] = {};

    for (int kt = 0; kt < nk; kt++) {
        #pragma unroll
        for (int l = 0; l < 4; l++) {
            int idx = tid + l*256; int row = idx >> 4, fc = idx & 15;
            *(uint4*)&Ks[row*QST + fc*4] =
                make_uint4(f2tf(rk[l].x), f2tf(rk[l].y), f2tf(rk[l].z), f2tf(rk[l].w));
            *(uint4*)&Vs[row*QST + fc*4] =
                make_uint4(f2tf(rv[l].x), f2tf(rv[l].y), f2tf(rv[l].z), f2tf(rv[l].w));
        }
        __syncthreads();

        if (kt + 1 < nk) {
            int koff = (kt + 1) << 6;
            #pragma unroll
            for (int l = 0; l < 4; l++) {
                int idx = tid + l*256; int row = idx >> 4, fc = idx & 15;
                rk[l] = *(const float4*)(Kp + ((koff + row) << 6) + fc*4);
                rv[l] = *(const float4*)(Vp + ((koff + row) << 6) + fc*4);
            }
        }

        // ---- S = Q K^T ----
        float s[8][4] = {};
        #pragma unroll
        for (int ik = 0; ik < 8; ik++) {
            #pragma unroll
            for (int in = 0; in < 8; in++) {
                const unsigned* p = &Ks[(in*8 + g)*QST + ik*8];
                mma_tf32(s[in], qa[ik][0], qa[ik][1], qa[ik][2], qa[ik][3],
                         p[tig], p[tig + 4]);
            }
        }

        // ---- causal mask (last two tiles only) ----
        if (kt >= nk - 2) {
            int rbase = q0 + warp*16 + g;
            #pragma unroll
            for (int in = 0; in < 8; in++) {
                int cb = (kt << 6) + in*8 + tig*2;
                if (cb     > rbase)     s[in][0] = -1e30f;
                if (cb + 1 > rbase)     s[in][1] = -1e30f;
                if (cb     > rbase + 8) s[in][2] = -1e30f;
                if (cb + 1 > rbase + 8) s[in][3] = -1e30f;
            }
        }

        // ---- online softmax (rows g and g+8; reduce over 4-lane tig group) --
        float mx0 = -1e30f, mx1 = -1e30f;
        #pragma unroll
        for (int in = 0; in < 8; in++) {
            mx0 = fmaxf(mx0, fmaxf(s[in][0], s[in][1]));
            mx1 = fmaxf(mx1, fmaxf(s[in][2], s[in][3]));
        }
        mx0 = fmaxf(mx0, __shfl_xor_sync(0xffffffffu, mx0, 1));
        mx0 = fmaxf(mx0, __shfl_xor_sync(0xffffffffu, mx0, 2));
        mx1 = fmaxf(mx1, __shfl_xor_sync(0xffffffffu, mx1, 1));
        mx1 = fmaxf(mx1, __shfl_xor_sync(0xffffffffu, mx1, 2));
        float mn0 = fmaxf(m0r, mx0), mn1 = fmaxf(m1r, mx1);
        float c0 = __expf(m0r - mn0), c1 = __expf(m1r - mn1);
        float s0 = 0.f, s1 = 0.f;
        #pragma unroll
        for (int in = 0; in < 8; in++) {
            s[in][0] = __expf(s[in][0] - mn0); s0 += s[in][0];
            s[in][1] = __expf(s[in][1] - mn0); s0 += s[in][1];
            s[in][2] = __expf(s[in][2] - mn1); s1 += s[in][2];
            s[in][3] = __expf(s[in][3] - mn1); s1 += s[in][3];
        }
        s0 += __shfl_xor_sync(0xffffffffu, s0, 1);
        s0 += __shfl_xor_sync(0xffffffffu, s0, 2);
        s1 += __shfl_xor_sync(0xffffffffu, s1, 1);
        s1 += __shfl_xor_sync(0xffffffffu, s1, 2);
        l0r = l0r*c0 + s0; l1r = l1r*c1 + s1;
        m0r = mn0; m1r = mn1;
        #pragma unroll
        for (int dn = 0; dn < 8; dn++) {
            O[dn][0] *= c0; O[dn][1] *= c0; O[dn][2] *= c1; O[dn][3] *= c1;
        }

        // ---- C-frag -> A-frag transpose of P, in registers (8 shfls/tile) ---
        int srl = (lane & 28) | (tig >> 1);
        int srh = srl + 2;
        #pragma unroll
        for (int j = 0; j < 8; j++) {
            float e00 = __shfl_sync(0xffffffffu, s[j][0], srl);
            float e01 = __shfl_sync(0xffffffffu, s[j][1], srl);
            float e20 = __shfl_sync(0xffffffffu, s[j][2], srl);
            float e21 = __shfl_sync(0xffffffffu, s[j][3], srl);
            float f00 = __shfl_sync(0xffffffffu, s[j][0], srh);
            float f01 = __shfl_sync(0xffffffffu, s[j][1], srh);
            float f20 = __shfl_sync(0xffffffffu, s[j][2], srh);
            float f21 = __shfl_sync(0xffffffffu, s[j][3], srh);
            bool od = (tig & 1);
            s[j][0] = __uint_as_float(f2tf(od ? e01 : e00));
            s[j][1] = __uint_as_float(f2tf(od ? e21 : e20));
            s[j][2] = __uint_as_float(f2tf(od ? f01 : f00));
            s[j][3] = __uint_as_float(f2tf(od ? f21 : f20));
        }

        // ---- O += P V ----
        #pragma unroll
        for (int j = 0; j < 8; j++) {
            #pragma unroll
            for (int dn = 0; dn < 8; dn++) {
                const unsigned* p = &Vs[(j*8 + tig)*QST + dn*8 + g];
                mma_tf32(O[dn],
                         __float_as_uint(s[j][0]), __float_as_uint(s[j][1]),
                         __float_as_uint(s[j][2]), __float_as_uint(s[j][3]),
                         p[0], p[4*QST]);
            }
        }
        __syncthreads();   // before next tile overwrites Ks/Vs
    }

    // ---- epilogue ----
    float i0 = 1.0f / l0r, i1 = 1.0f / l1r;
    int b = bh >> 3, h = bh & 7;
    int r0 = q0 + warp*16 + g;
    #pragma unroll
    for (int dn = 0; dn < 8; dn++) {
        int col = h*64 + dn*8 + tig*2;
        *(float2*)(g_y + (b*TSEQ + r0    )*CDIM + col) =
            make_float2(O[dn][0]*i0, O[dn][1]*i0);
        *(float2*)(g_y + (b*TSEQ + r0 + 8)*CDIM + col) =
            make_float2(O[dn][2]*i1, O[dn][3]*i1);
    }
}

// ---------------------------------------------------------------------------
// Inputs: x, weight, state, Wq, bq, Wk, bk, Wv, bv, Wp, bp
// ---------------------------------------------------------------------------
extern "C" void kernel_launch(void* const* d_in, const int* in_sizes, int n_in,
                              void* d_out, int out_size)
{
    (void)in_sizes; (void)n_in; (void)out_size;
    const float* x  = (const float*)d_in[0];
    const float* Wq = (const float*)d_in[3];
    const float* bq = (const float*)d_in[4];
    const float* Wk = (const float*)d_in[5];
    const float* bk = (const float*)d_in[6];
    const float* Wv = (const float*)d_in[7];
    const float* bv = (const float*)d_in[8];
    const float* Wp = (const float*)d_in[9];
    const float* bp = (const float*)d_in[10];
    float* out = (float*)d_out;

    dim3 gg(CDIM/64, MROWS/128);           // (8, 64)
    gemm_tf32<0><<<gg, 256>>>(x, Wq, bq, nullptr);
    gemm_tf32<1><<<gg, 256>>>(x, Wk, bk, nullptr);
    gemm_tf32<2><<<gg, 256>>>(x, Wv, bv, nullptr);

    dim3 ga(TSEQ/128, BBATCH*NHEAD);       // (32, 16)
    attn_tf32<<<ga, 256>>>();

    gemm_tf32<3><<<gg, 256>>>(nullptr, Wp, bp, out);
}

// round 6
// speedup vs baseline: 3.4384x; 1.2470x over previous
#include <cuda_runtime.h>
#include <cstdint>

#define BBATCH 2
#define TSEQ   4096
#define CDIM   512
#define NHEAD  8
#define HDIM   64
#define MROWS  (BBATCH*TSEQ)

// Q scale: 1/sqrt(64) * log2(e)  (softmax done in exp2 domain)
#define QSCALE 0.18033688011112042f

// Internal scratch (device globals: allocation-free rule)
__device__ float g_q[BBATCH*NHEAD*TSEQ*HDIM];   // tf32-rounded, pre-scaled
__device__ float g_k[BBATCH*NHEAD*TSEQ*HDIM];   // tf32-rounded
__device__ float g_v[BBATCH*NHEAD*TSEQ*HDIM];   // tf32-rounded, rows permuted in 8-groups
__device__ float g_y[BBATCH*TSEQ*CDIM];

__device__ __forceinline__ unsigned f2tf(float x){
    unsigned u; asm("cvt.rna.tf32.f32 %0, %1;" : "=r"(u) : "f"(x)); return u;
}
__device__ __forceinline__ float ex2(float x){
    float r; asm("ex2.approx.f32 %0, %1;" : "=f"(r) : "f"(x)); return r;
}
__device__ __forceinline__ void mma_tf32(float c[4],
    unsigned a0, unsigned a1, unsigned a2, unsigned a3,
    unsigned b0, unsigned b1)
{
    asm volatile(
        "mma.sync.aligned.m16n8k8.row.col.f32.tf32.tf32.f32 "
        "{%0,%1,%2,%3}, {%4,%5,%6,%7}, {%8,%9}, {%0,%1,%2,%3};"
        : "+f"(c[0]), "+f"(c[1]), "+f"(c[2]), "+f"(c[3])
        : "r"(a0), "r"(a1), "r"(a2), "r"(a3), "r"(b0), "r"(b1));
}
__device__ __forceinline__ void cpa16(float* dst, const float* src){
    unsigned d = (unsigned)__cvta_generic_to_shared(dst);
    asm volatile("cp.async.ca.shared.global [%0], [%1], 16;\n" :: "r"(d), "l"(src));
}
#define CP_COMMIT()  asm volatile("cp.async.commit_group;\n")
#define CP_WAIT(N)   asm volatile("cp.async.wait_group %0;\n" :: "n"(N))

// ---------------------------------------------------------------------------
// GEMM: out = A @ W^T + bias.  M=8192, N=512, K=512.  (unchanged core from R2)
// MODE 0: -> g_q (scaled+tf32) | 1: -> g_k (tf32) | 2: -> g_v (tf32, row-perm)
// MODE 3: A = g_y, row-major fp32 out.
// ---------------------------------------------------------------------------
#define GST 36

template<int MODE>
__global__ __launch_bounds__(256,2) void gemm_tf32(
    const float* __restrict__ Ain, const float* __restrict__ W,
    const float* __restrict__ bias, float* __restrict__ outp)
{
    __shared__ unsigned sA[128*GST];
    __shared__ unsigned sB[64*GST];

    const float* __restrict__ A = (MODE == 3) ? (const float*)g_y : Ain;
    float* __restrict__ out =
        (MODE == 0) ? g_q : (MODE == 1) ? g_k : (MODE == 2) ? g_v : outp;

    const int tid = threadIdx.x, lane = tid & 31, warp = tid >> 5;
    const int wm = warp >> 1, wn = warp & 1;
    const int g = lane >> 2, tig = lane & 3;
    const int m0 = blockIdx.y * 128, n0 = blockIdx.x * 64;

    float acc[2][4][4] = {};

    float4 ra[4], rb[2];
    #pragma unroll
    for (int l = 0; l < 4; l++) {
        int idx = tid + l*256;
        ra[l] = *(const float4*)(A + (m0 + (idx>>3))*CDIM + ((idx&7)<<2));
    }
    #pragma unroll
    for (int l = 0; l < 2; l++) {
        int idx = tid + l*256;
        rb[l] = *(const float4*)(W + (n0 + (idx>>3))*CDIM + ((idx&7)<<2));
    }

    for (int it = 0; it < 16; it++) {
        #pragma unroll
        for (int l = 0; l < 4; l++) {
            int idx = tid + l*256; int row = idx>>3, k0 = (idx&7)<<2;
            *(uint4*)&sA[row*GST + k0] =
                make_uint4(f2tf(ra[l].x), f2tf(ra[l].y), f2tf(ra[l].z), f2tf(ra[l].w));
        }
        #pragma unroll
        for (int l = 0; l < 2; l++) {
            int idx = tid + l*256; int row = idx>>3, k0 = (idx&7)<<2;
            *(uint4*)&sB[row*GST + k0] =
                make_uint4(f2tf(rb[l].x), f2tf(rb[l].y), f2tf(rb[l].z), f2tf(rb[l].w));
        }
        __syncthreads();

        if (it < 15) {
            int kb = (it+1) * 32;
            #pragma unroll
            for (int l = 0; l < 4; l++) {
                int idx = tid + l*256;
                ra[l] = *(const float4*)(A + (m0 + (idx>>3))*CDIM + kb + ((idx&7)<<2));
            }
            #pragma unroll
            for (int l = 0; l < 2; l++) {
                int idx = tid + l*256;
                rb[l] = *(const float4*)(W + (n0 + (idx>>3))*CDIM + kb + ((idx&7)<<2));
            }
        }

        #pragma unroll
        for (int ik = 0; ik < 4; ik++) {
            unsigned a[2][4];
            #pragma unroll
            for (int mt = 0; mt < 2; mt++) {
                const unsigned* p = &sA[(wm*32 + mt*16)*GST + ik*8];
                a[mt][0] = p[g*GST + tig];
                a[mt][1] = p[(g+8)*GST + tig];
                a[mt][2] = p[g*GST + tig + 4];
                a[mt][3] = p[(g+8)*GST + tig + 4];
            }
            #pragma unroll
            for (int nt = 0; nt < 4; nt++) {
                const unsigned* p = &sB[(wn*32 + nt*8)*GST + ik*8];
                unsigned b0 = p[g*GST + tig], b1 = p[g*GST + tig + 4];
                mma_tf32(acc[0][nt], a[0][0], a[0][1], a[0][2], a[0][3], b0, b1);
                mma_tf32(acc[1][nt], a[1][0], a[1][1], a[1][2], a[1][3], b0, b1);
            }
        }
        __syncthreads();
    }

    #pragma unroll
    for (int mt = 0; mt < 2; mt++) {
        #pragma unroll
        for (int r = 0; r < 2; r++) {
            int row = m0 + wm*32 + mt*16 + g + r*8;
            #pragma unroll
            for (int nt = 0; nt < 4; nt++) {
                int col = n0 + wn*32 + nt*8 + tig*2;
                float2 bv = *(const float2*)(bias + col);
                float vx = acc[mt][nt][r*2+0] + bv.x;
                float vy = acc[mt][nt][r*2+1] + bv.y;
                if (MODE == 3) {
                    *(float2*)(out + row*CDIM + col) = make_float2(vx, vy);
                } else {
                    if (MODE == 0) { vx *= QSCALE; vy *= QSCALE; }
                    vx = __uint_as_float(f2tf(vx));
                    vy = __uint_as_float(f2tf(vy));
                    int b = row >> 12, t = row & 4095, h = col >> 6, d = col & 63;
                    if (MODE == 2) {
                        int k = t & 7;                       // invmap: key k -> slot
                        t = (t & ~7) | ((k >> 1) | ((k & 1) << 2));
                    }
                    *(float2*)(out + (((b*NHEAD + h)*TSEQ + t) << 6) + d) =
                        make_float2(vx, vy);
                }
            }
        }
    }
}

// ---------------------------------------------------------------------------
// Flash attention, tf32 mma.  Block = 128 q-rows x (b,h).  8 warps x 16 rows.
// Q/K/V arrive tf32-rounded (Q pre-scaled).  K/V double-buffered via cp.async.
// K stride 68 (bank 4g+tig, conflict-free), V stride 72 (bank 8tig+g, c-f).
// P fed to PV-mma directly from C-fragments (V rows pre-permuted in gmem).
// ---------------------------------------------------------------------------
#define KSTR 68
#define VSTR 72
#define STG  (64*KSTR + 64*VSTR)   // floats per stage = 8960

__global__ __launch_bounds__(256,1) void attn_tf32()
{
    extern __shared__ float sm[];   // 2 * STG floats = 71680 B

    const int tid = threadIdx.x, lane = tid & 31, warp = tid >> 5;
    const int g = lane >> 2, tig = lane & 3;
    const int qi = (TSEQ/128 - 1) - blockIdx.x;    // big tiles first
    const int bh = blockIdx.y;
    const int q0 = qi * 128;
    const float* __restrict__ Qp = g_q + bh*(TSEQ*HDIM);
    const float* __restrict__ Kp = g_k + bh*(TSEQ*HDIM);
    const float* __restrict__ Vp = g_v + bh*(TSEQ*HDIM);

    // ---- stage Q (async copy into stage-0 region), load A-fragments ----
    #pragma unroll
    for (int l = 0; l < 8; l++) {
        int id = tid + l*256; int row = id >> 4, c = id & 15;
        cpa16(sm + row*KSTR + c*4, Qp + ((q0 + row) << 6) + c*4);
    }
    CP_COMMIT();
    CP_WAIT(0);
    __syncthreads();

    unsigned qa[8][4];
    {
        const unsigned* Qs = (const unsigned*)sm;
        #pragma unroll
        for (int ik = 0; ik < 8; ik++) {
            const unsigned* p = Qs + (warp*16)*KSTR + ik*8;
            qa[ik][0] = p[g*KSTR + tig];
            qa[ik][1] = p[(g+8)*KSTR + tig];
            qa[ik][2] = p[g*KSTR + tig + 4];
            qa[ik][3] = p[(g+8)*KSTR + tig + 4];
        }
    }
    __syncthreads();   // all warps done with Q before stage-0 overwrite

    const int nk = (q0 >> 6) + 2;

    // async copy of tile kt into stage s
    auto copy_tile = [&](int kt, int s) {
        const int ko = kt << 12;                  // kt*64*64
        float* Kd = sm + s*STG;
        float* Vd = Kd + 64*KSTR;
        #pragma unroll
        for (int l = 0; l < 4; l++) {
            int id = tid + l*256; int row = id >> 4, c = id & 15;
            cpa16(Kd + row*KSTR + c*4, Kp + ko + (row << 6) + c*4);
        }
        #pragma unroll
        for (int l = 0; l < 4; l++) {
            int id = tid + l*256; int row = id >> 4, c = id & 15;
            cpa16(Vd + row*VSTR + c*4, Vp + ko + (row << 6) + c*4);
        }
        CP_COMMIT();
    };

    copy_tile(0, 0);

    float m0r = -1e30f, m1r = -1e30f, l0r = 0.f, l1r = 0.f;
    float O[8][4] = {};

    for (int kt = 0; kt < nk; kt++) {
        const int s = kt & 1;
        if (kt + 1 < nk) { copy_tile(kt + 1, s ^ 1); CP_WAIT(1); }
        else             { CP_WAIT(0); }
        __syncthreads();

        const unsigned* Ks = (const unsigned*)(sm + s*STG);
        const unsigned* Vs = Ks + 64*KSTR;

        // ---- S = Q K^T ----
        float sc[8][4] = {};
        #pragma unroll
        for (int ik = 0; ik < 8; ik++) {
            #pragma unroll
            for (int in = 0; in < 8; in++) {
                const unsigned* p = Ks + (in*8 + g)*KSTR + ik*8;
                mma_tf32(sc[in], qa[ik][0], qa[ik][1], qa[ik][2], qa[ik][3],
                         p[tig], p[tig + 4]);
            }
        }

        // ---- causal mask (last two tiles only) ----
        if (kt >= nk - 2) {
            int rbase = q0 + warp*16 + g;
            #pragma unroll
            for (int in = 0; in < 8; in++) {
                int cb = (kt << 6) + in*8 + tig*2;
                if (cb     > rbase)     sc[in][0] = -1e30f;
                if (cb + 1 > rbase)     sc[in][1] = -1e30f;
                if (cb     > rbase + 8) sc[in][2] = -1e30f;
                if (cb + 1 > rbase + 8) sc[in][3] = -1e30f;
            }
        }

        // ---- online softmax in exp2 domain (rows g, g+8; reduce over tig) ---
        float mx0 = -1e30f, mx1 = -1e30f;
        #pragma unroll
        for (int in = 0; in < 8; in++) {
            mx0 = fmaxf(mx0, fmaxf(sc[in][0], sc[in][1]));
            mx1 = fmaxf(mx1, fmaxf(sc[in][2], sc[in][3]));
        }
        mx0 = fmaxf(mx0, __shfl_xor_sync(0xffffffffu, mx0, 1));
        mx0 = fmaxf(mx0, __shfl_xor_sync(0xffffffffu, mx0, 2));
        mx1 = fmaxf(mx1, __shfl_xor_sync(0xffffffffu, mx1, 1));
        mx1 = fmaxf(mx1, __shfl_xor_sync(0xffffffffu, mx1, 2));
        float mn0 = fmaxf(m0r, mx0), mn1 = fmaxf(m1r, mx1);
        float c0 = ex2(m0r - mn0), c1 = ex2(m1r - mn1);
        float s0 = 0.f, s1 = 0.f;
        #pragma unroll
        for (int in = 0; in < 8; in++) {
            sc[in][0] = ex2(sc[in][0] - mn0); s0 += sc[in][0];
            sc[in][1] = ex2(sc[in][1] - mn0); s0 += sc[in][1];
            sc[in][2] = ex2(sc[in][2] - mn1); s1 += sc[in][2];
            sc[in][3] = ex2(sc[in][3] - mn1); s1 += sc[in][3];
        }
        s0 += __shfl_xor_sync(0xffffffffu, s0, 1);
        s0 += __shfl_xor_sync(0xffffffffu, s0, 2);
        s1 += __shfl_xor_sync(0xffffffffu, s1, 1);
        s1 += __shfl_xor_sync(0xffffffffu, s1, 2);
        l0r = l0r*c0 + s0; l1r = l1r*c1 + s1;
        m0r = mn0; m1r = mn1;
        #pragma unroll
        for (int dn = 0; dn < 8; dn++) {
            O[dn][0] *= c0; O[dn][1] *= c0; O[dn][2] *= c1; O[dn][3] *= c1;
        }

        // ---- O += P V : C-frag feeds A directly (V rows pre-permuted) ------
        #pragma unroll
        for (int j = 0; j < 8; j++) {
            unsigned a0 = f2tf(sc[j][0]);   // P[g   ][2tig  ]
            unsigned a1 = f2tf(sc[j][2]);   // P[g+8 ][2tig  ]
            unsigned a2 = f2tf(sc[j][1]);   // P[g   ][2tig+1]
            unsigned a3 = f2tf(sc[j][3]);   // P[g+8 ][2tig+1]
            #pragma unroll
            for (int dn = 0; dn < 8; dn++) {
                const unsigned* p = Vs + (j*8 + tig)*VSTR + dn*8 + g;
                mma_tf32(O[dn], a0, a1, a2, a3, p[0], p[4*VSTR]);
            }
        }
        __syncthreads();   // all reads of stage s done before its next overwrite
    }

    // ---- epilogue ----
    float i0 = 1.0f / l0r, i1 = 1.0f / l1r;
    int b = bh >> 3, h = bh & 7;
    int r0 = q0 + warp*16 + g;
    #pragma unroll
    for (int dn = 0; dn < 8; dn++) {
        int col = h*64 + dn*8 + tig*2;
        *(float2*)(g_y + (b*TSEQ + r0    )*CDIM + col) =
            make_float2(O[dn][0]*i0, O[dn][1]*i0);
        *(float2*)(g_y + (b*TSEQ + r0 + 8)*CDIM + col) =
            make_float2(O[dn][2]*i1, O[dn][3]*i1);
    }
}

// ---------------------------------------------------------------------------
// Inputs: x, weight, state, Wq, bq, Wk, bk, Wv, bv, Wp, bp
// ---------------------------------------------------------------------------
extern "C" void kernel_launch(void* const* d_in, const int* in_sizes, int n_in,
                              void* d_out, int out_size)
{
    (void)in_sizes; (void)n_in; (void)out_size;
    const float* x  = (const float*)d_in[0];
    const float* Wq = (const float*)d_in[3];
    const float* bq = (const float*)d_in[4];
    const float* Wk = (const float*)d_in[5];
    const float* bk = (const float*)d_in[6];
    const float* Wv = (const float*)d_in[7];
    const float* bv = (const float*)d_in[8];
    const float* Wp = (const float*)d_in[9];
    const float* bp = (const float*)d_in[10];
    float* out = (float*)d_out;

    static bool attr_done = false;
    if (!attr_done) {
        cudaFuncSetAttribute(attn_tf32,
            cudaFuncAttributeMaxDynamicSharedMemorySize, 2*STG*sizeof(float));
        attr_done = true;
    }

    dim3 gg(CDIM/64, MROWS/128);           // (8, 64)
    gemm_tf32<0><<<gg, 256>>>(x, Wq, bq, nullptr);
    gemm_tf32<1><<<gg, 256>>>(x, Wk, bk, nullptr);
    gemm_tf32<2><<<gg, 256>>>(x, Wv, bv, nullptr);

    dim3 ga(TSEQ/128, BBATCH*NHEAD);       // (32, 16)
    attn_tf32<<<ga, 256, 2*STG*sizeof(float)>>>();

    gemm_tf32<3><<<gg, 256>>>(nullptr, Wp, bp, out);
}

// round 8
// speedup vs baseline: 5.1029x; 1.4841x over previous
#include <cuda_runtime.h>
#include <cuda_fp16.h>
#include <cstdint>

#define BBATCH 2
#define TSEQ   4096
#define CDIM   512
#define NHEAD  8
#define HDIM   64
#define MROWS  (BBATCH*TSEQ)

// Q scale: 1/sqrt(64) * log2(e)  (softmax in exp2 domain)
#define QSCALE 0.18033688011112042f

// Internal scratch (device globals: allocation-free rule). All half.
__device__ __half g_q[BBATCH*NHEAD*TSEQ*HDIM];   // [b,h,t,d], pre-scaled
__device__ __half g_k[BBATCH*NHEAD*TSEQ*HDIM];   // [b,h,t,d]
__device__ __half g_v[BBATCH*NHEAD*HDIM*TSEQ];   // [b,h,d,t]  (transposed!)
__device__ __half g_y[BBATCH*TSEQ*CDIM];         // attention out, half

__device__ __forceinline__ float ex2(float x){
    float r; asm("ex2.approx.f32 %0, %1;" : "=f"(r) : "f"(x)); return r;
}
__device__ __forceinline__ unsigned packh2(float a, float b){
    __half2 h = __floats2half2_rn(a, b); return *(unsigned*)&h;
}
__device__ __forceinline__ void mma_f16(float c[4],
    unsigned a0, unsigned a1, unsigned a2, unsigned a3,
    unsigned b0, unsigned b1)
{
    asm volatile(
        "mma.sync.aligned.m16n8k16.row.col.f32.f16.f16.f32 "
        "{%0,%1,%2,%3}, {%4,%5,%6,%7}, {%8,%9}, {%0,%1,%2,%3};"
        : "+f"(c[0]), "+f"(c[1]), "+f"(c[2]), "+f"(c[3])
        : "r"(a0), "r"(a1), "r"(a2), "r"(a3), "r"(b0), "r"(b1));
}
__device__ __forceinline__ void cpa16(void* dst, const void* src){
    unsigned d = (unsigned)__cvta_generic_to_shared(dst);
    asm volatile("cp.async.ca.shared.global [%0], [%1], 16;\n" :: "r"(d), "l"(src));
}
#define CP_COMMIT()  asm volatile("cp.async.commit_group;\n")
#define CP_WAIT(N)   asm volatile("cp.async.wait_group %0;\n" :: "n"(N))

// ---------------------------------------------------------------------------
// GEMM: out = A @ W^T + bias.  M=8192, N=512, K=512, fp16 mma, fp32 accum.
// Block 128x64, BK=32, 256 thr = 8 warps (4M x 2N), warp 32x32.
// Smem half, stride 40 halves (word bank 20g+tig: injective mod 32).
// MODE 0: ->g_q (scaled, half)  1: ->g_k (half)  2: ->g_v (half, TRANSPOSED)
// MODE 3: A = g_y (half), out = fp32 row-major.
// ---------------------------------------------------------------------------
#define GSTH 40

template<int MODE>
__global__ __launch_bounds__(256,2) void gemm_f16(
    const float* __restrict__ Ain, const float* __restrict__ W,
    const float* __restrict__ bias, float* __restrict__ outp)
{
    __shared__ __half sA[128*GSTH];
    __shared__ __half sB[64*GSTH];

    const int tid = threadIdx.x, lane = tid & 31, warp = tid >> 5;
    const int wm = warp >> 1, wn = warp & 1;
    const int g = lane >> 2, tig = lane & 3;
    const int m0 = blockIdx.y * 128, n0 = blockIdx.x * 64;

    float acc[2][4][4] = {};

    float4 ra[4]; uint4 rah[2]; float4 rb[2];
    if (MODE == 3) {
        #pragma unroll
        for (int l = 0; l < 2; l++) {
            int id = tid + l*256;                    // 128 rows x 4 chunks(8h)
            rah[l] = *(const uint4*)(g_y + (m0 + (id>>2))*CDIM + (id&3)*8);
        }
    } else {
        #pragma unroll
        for (int l = 0; l < 4; l++) {
            int id = tid + l*256;
            ra[l] = *(const float4*)(Ain + (m0 + (id>>3))*CDIM + ((id&7)<<2));
        }
    }
    #pragma unroll
    for (int l = 0; l < 2; l++) {
        int id = tid + l*256;
        rb[l] = *(const float4*)(W + (n0 + (id>>3))*CDIM + ((id&7)<<2));
    }

    for (int it = 0; it < 16; it++) {
        if (MODE == 3) {
            #pragma unroll
            for (int l = 0; l < 2; l++) {
                int id = tid + l*256;
                *(uint4*)&sA[(id>>2)*GSTH + (id&3)*8] = rah[l];
            }
        } else {
            #pragma unroll
            for (int l = 0; l < 4; l++) {
                int id = tid + l*256; int row = id>>3, kc = (id&7)<<2;
                *(uint2*)&sA[row*GSTH + kc] = make_uint2(
                    packh2(ra[l].x, ra[l].y), packh2(ra[l].z, ra[l].w));
            }
        }
        #pragma unroll
        for (int l = 0; l < 2; l++) {
            int id = tid + l*256; int row = id>>3, kc = (id&7)<<2;
            *(uint2*)&sB[row*GSTH + kc] = make_uint2(
                packh2(rb[l].x, rb[l].y), packh2(rb[l].z, rb[l].w));
        }
        __syncthreads();

        if (it < 15) {
            int kb = (it+1) * 32;
            if (MODE == 3) {
                #pragma unroll
                for (int l = 0; l < 2; l++) {
                    int id = tid + l*256;
                    rah[l] = *(const uint4*)(g_y + (m0 + (id>>2))*CDIM + kb + (id&3)*8);
                }
            } else {
                #pragma unroll
                for (int l = 0; l < 4; l++) {
                    int id = tid + l*256;
                    ra[l] = *(const float4*)(Ain + (m0 + (id>>3))*CDIM + kb + ((id&7)<<2));
                }
            }
            #pragma unroll
            for (int l = 0; l < 2; l++) {
                int id = tid + l*256;
                rb[l] = *(const float4*)(W + (n0 + (id>>3))*CDIM + kb + ((id&7)<<2));
            }
        }

        #pragma unroll
        for (int u = 0; u < 2; u++) {
            unsigned a[2][4];
            #pragma unroll
            for (int mt = 0; mt < 2; mt++) {
                const __half* p = &sA[(wm*32 + mt*16)*GSTH + 16*u];
                a[mt][0] = *(const unsigned*)&p[g*GSTH + 2*tig];
                a[mt][1] = *(const unsigned*)&p[(g+8)*GSTH + 2*tig];
                a[mt][2] = *(const unsigned*)&p[g*GSTH + 2*tig + 8];
                a[mt][3] = *(const unsigned*)&p[(g+8)*GSTH + 2*tig + 8];
            }
            #pragma unroll
            for (int nt = 0; nt < 4; nt++) {
                const __half* q = &sB[(wn*32 + nt*8)*GSTH + 16*u];
                unsigned b0 = *(const unsigned*)&q[g*GSTH + 2*tig];
                unsigned b1 = *(const unsigned*)&q[g*GSTH + 2*tig + 8];
                mma_f16(acc[0][nt], a[0][0], a[0][1], a[0][2], a[0][3], b0, b1);
                mma_f16(acc[1][nt], a[1][0], a[1][1], a[1][2], a[1][3], b0, b1);
            }
        }
        __syncthreads();
    }

    #pragma unroll
    for (int mt = 0; mt < 2; mt++) {
        #pragma unroll
        for (int r = 0; r < 2; r++) {
            int row = m0 + wm*32 + mt*16 + g + r*8;
            #pragma unroll
            for (int nt = 0; nt < 4; nt++) {
                int col = n0 + wn*32 + nt*8 + tig*2;
                float2 bv = *(const float2*)(bias + col);
                float vx = acc[mt][nt][r*2+0] + bv.x;
                float vy = acc[mt][nt][r*2+1] + bv.y;
                if (MODE == 3) {
                    *(float2*)(outp + row*CDIM + col) = make_float2(vx, vy);
                } else {
                    int b = row >> 12, t = row & 4095, h = col >> 6, d = col & 63;
                    if (MODE == 0) { vx *= QSCALE; vy *= QSCALE; }
                    if (MODE == 2) {
                        // transposed: g_v[(bh*64 + d)*TSEQ + t]
                        __half* vp = g_v + (((b*NHEAD + h)*HDIM + d)*TSEQ) + t;
                        vp[0]    = __float2half_rn(vx);
                        vp[TSEQ] = __float2half_rn(vy);
                    } else {
                        __half* op = (MODE == 0) ? g_q : g_k;
                        *(unsigned*)&op[(((b*NHEAD + h)*TSEQ + t) << 6) + d] =
                            packh2(vx, vy);
                    }
                }
            }
        }
    }
}

// ---------------------------------------------------------------------------
// Flash attention, fp16 mma (m16n8k16), fp32 softmax/accum.
// Block = 128 q-rows x (b,h).  8 warps x 16 rows.  2 CTAs/SM.
// K [key][d] and V [d][key] (pre-transposed) in smem, stride 72 halves
// (word bank 4g+tig+8u: conflict-free).  cp.async double buffering.
// P feeds PV A-fragments directly from S C-fragments (no shuffles).
// ---------------------------------------------------------------------------
#define AST    72
#define STAGEH (64*AST*2)     // halves per stage (K tile + V tile) = 9216

__global__ __launch_bounds__(256,2) void attn_f16()
{
    extern __shared__ __half sm[];   // 2 stages = 18432 halves = 36864 B

    const int tid = threadIdx.x, lane = tid & 31, warp = tid >> 5;
    const int g = lane >> 2, tig = lane & 3;
    const int qi = (TSEQ/128 - 1) - blockIdx.x;     // big tiles first
    const int bh = blockIdx.y;
    const int q0 = qi * 128;
    const __half* __restrict__ Qp = g_q + bh*(TSEQ*HDIM);
    const __half* __restrict__ Kp = g_k + bh*(TSEQ*HDIM);
    const __half* __restrict__ Vp = g_v + bh*(HDIM*TSEQ);

    // ---- stage Q into stage-0 (exactly one stage worth), load A-frags ----
    #pragma unroll
    for (int l = 0; l < 4; l++) {
        int id = tid + l*256; int row = id >> 3, c = id & 7;
        cpa16(sm + row*AST + c*8, Qp + ((q0 + row) << 6) + c*8);
    }
    CP_COMMIT();
    CP_WAIT(0);
    __syncthreads();

    unsigned qa[4][4];
    #pragma unroll
    for (int u = 0; u < 4; u++) {
        const __half* p = sm + (warp*16)*AST + 16*u;
        qa[u][0] = *(const unsigned*)&p[g*AST + 2*tig];
        qa[u][1] = *(const unsigned*)&p[(g+8)*AST + 2*tig];
        qa[u][2] = *(const unsigned*)&p[g*AST + 2*tig + 8];
        qa[u][3] = *(const unsigned*)&p[(g+8)*AST + 2*tig + 8];
    }
    __syncthreads();   // all warps done with Q before stage-0 overwrite

    const int nk = (q0 >> 6) + 2;

    auto copy_tile = [&](int kt, int s) {
        const int k0 = kt << 6;
        __half* Kd = sm + s*STAGEH;
        __half* Vd = Kd + 64*AST;
        #pragma unroll
        for (int l = 0; l < 2; l++) {
            int id = tid + l*256; int row = id >> 3, c = id & 7;
            cpa16(Kd + row*AST + c*8, Kp + ((k0 + row) << 6) + c*8);
        }
        #pragma unroll
        for (int l = 0; l < 2; l++) {
            int id = tid + l*256; int row = id >> 3, c = id & 7;
            cpa16(Vd + row*AST + c*8, Vp + row*TSEQ + k0 + c*8);
        }
        CP_COMMIT();
    };

    copy_tile(0, 0);

    float m0r = -1e30f, m1r = -1e30f, l0r = 0.f, l1r = 0.f;
    float O[8][4] = {};

    for (int kt = 0; kt < nk; kt++) {
        const int s = kt & 1;
        if (kt + 1 < nk) { copy_tile(kt + 1, s ^ 1); CP_WAIT(1); }
        else             { CP_WAIT(0); }
        __syncthreads();

        const __half* Ks = sm + s*STAGEH;
        const __half* Vs = Ks + 64*AST;

        // ---- S = Q K^T ----
        float sc[8][4] = {};
        #pragma unroll
        for (int u = 0; u < 4; u++) {
            #pragma unroll
            for (int in = 0; in < 8; in++) {
                const __half* p = Ks + (in*8 + g)*AST + 16*u;
                mma_f16(sc[in], qa[u][0], qa[u][1], qa[u][2], qa[u][3],
                        *(const unsigned*)&p[2*tig],
                        *(const unsigned*)&p[2*tig + 8]);
            }
        }

        // ---- causal mask (last two tiles only) ----
        if (kt >= nk - 2) {
            int rbase = q0 + warp*16 + g;
            #pragma unroll
            for (int in = 0; in < 8; in++) {
                int cb = (kt << 6) + in*8 + tig*2;
                if (cb     > rbase)     sc[in][0] = -1e30f;
                if (cb + 1 > rbase)     sc[in][1] = -1e30f;
                if (cb     > rbase + 8) sc[in][2] = -1e30f;
                if (cb + 1 > rbase + 8) sc[in][3] = -1e30f;
            }
        }

        // ---- online softmax in exp2 domain (rows g, g+8; reduce over tig) --
        float mx0 = -1e30f, mx1 = -1e30f;
        #pragma unroll
        for (int in = 0; in < 8; in++) {
            mx0 = fmaxf(mx0, fmaxf(sc[in][0], sc[in][1]));
            mx1 = fmaxf(mx1, fmaxf(sc[in][2], sc[in][3]));
        }
        mx0 = fmaxf(mx0, __shfl_xor_sync(0xffffffffu, mx0, 1));
        mx0 = fmaxf(mx0, __shfl_xor_sync(0xffffffffu, mx0, 2));
        mx1 = fmaxf(mx1, __shfl_xor_sync(0xffffffffu, mx1, 1));
        mx1 = fmaxf(mx1, __shfl_xor_sync(0xffffffffu, mx1, 2));
        float mn0 = fmaxf(m0r, mx0), mn1 = fmaxf(m1r, mx1);
        float c0 = ex2(m0r - mn0), c1 = ex2(m1r - mn1);
        float s0 = 0.f, s1 = 0.f;
        #pragma unroll
        for (int in = 0; in < 8; in++) {
            sc[in][0] = ex2(sc[in][0] - mn0); s0 += sc[in][0];
            sc[in][1] = ex2(sc[in][1] - mn0); s0 += sc[in][1];
            sc[in][2] = ex2(sc[in][2] - mn1); s1 += sc[in][2];
            sc[in][3] = ex2(sc[in][3] - mn1); s1 += sc[in][3];
        }
        s0 += __shfl_xor_sync(0xffffffffu, s0, 1);
        s0 += __shfl_xor_sync(0xffffffffu, s0, 2);
        s1 += __shfl_xor_sync(0xffffffffu, s1, 1);
        s1 += __shfl_xor_sync(0xffffffffu, s1, 2);
        l0r = l0r*c0 + s0; l1r = l1r*c1 + s1;
        m0r = mn0; m1r = mn1;
        #pragma unroll
        for (int dn = 0; dn < 8; dn++) {
            O[dn][0] *= c0; O[dn][1] *= c0; O[dn][2] *= c1; O[dn][3] *= c1;
        }

        // ---- O += P V : pack C-frags straight into fp16 A-frags ----
        #pragma unroll
        for (int u = 0; u < 4; u++) {
            unsigned a0 = packh2(sc[2*u  ][0], sc[2*u  ][1]);
            unsigned a1 = packh2(sc[2*u  ][2], sc[2*u  ][3]);
            unsigned a2 = packh2(sc[2*u+1][0], sc[2*u+1][1]);
            unsigned a3 = packh2(sc[2*u+1][2], sc[2*u+1][3]);
            #pragma unroll
            for (int dn = 0; dn < 8; dn++) {
                const __half* p = Vs + (dn*8 + g)*AST + 16*u;
                mma_f16(O[dn], a0, a1, a2, a3,
                        *(const unsigned*)&p[2*tig],
                        *(const unsigned*)&p[2*tig + 8]);
            }
        }
        __syncthreads();   // stage s fully consumed before overwrite
    }

    // ---- epilogue: normalize, write half to g_y ----
    float i0 = 1.0f / l0r, i1 = 1.0f / l1r;
    int b = bh >> 3, h = bh & 7;
    int r0 = q0 + warp*16 + g;
    #pragma unroll
    for (int dn = 0; dn < 8; dn++) {
        int col = h*64 + dn*8 + tig*2;
        *(unsigned*)&g_y[(b*TSEQ + r0    )*CDIM + col] =
            packh2(O[dn][0]*i0, O[dn][1]*i0);
        *(unsigned*)&g_y[(b*TSEQ + r0 + 8)*CDIM + col] =
            packh2(O[dn][2]*i1, O[dn][3]*i1);
    }
}

// ---------------------------------------------------------------------------
// Inputs: x, weight, state, Wq, bq, Wk, bk, Wv, bv, Wp, bp
// ---------------------------------------------------------------------------
extern "C" void kernel_launch(void* const* d_in, const int* in_sizes, int n_in,
                              void* d_out, int out_size)
{
    (void)in_sizes; (void)n_in; (void)out_size;
    const float* x  = (const float*)d_in[0];
    const float* Wq = (const float*)d_in[3];
    const float* bq = (const float*)d_in[4];
    const float* Wk = (const float*)d_in[5];
    const float* bk = (const float*)d_in[6];
    const float* Wv = (const float*)d_in[7];
    const float* bv = (const float*)d_in[8];
    const float* Wp = (const float*)d_in[9];
    const float* bp = (const float*)d_in[10];
    float* out = (float*)d_out;

    dim3 gg(CDIM/64, MROWS/128);           // (8, 64)
    gemm_f16<0><<<gg, 256>>>(x, Wq, bq, nullptr);
    gemm_f16<1><<<gg, 256>>>(x, Wk, bk, nullptr);
    gemm_f16<2><<<gg, 256>>>(x, Wv, bv, nullptr);

    dim3 ga(TSEQ/128, BBATCH*NHEAD);       // (32, 16)
    attn_f16<<<ga, 256, STAGEH*2*sizeof(__half)>>>();

    gemm_f16<3><<<gg, 256>>>(nullptr, Wp, bp, out);
}

// round 11
// speedup vs baseline: 5.6726x; 1.1116x over previous
#include <cuda_runtime.h>
#include <cuda_fp16.h>
#include <cstdint>

#define BBATCH 2
#define TSEQ   4096
#define CDIM   512
#define NHEAD  8
#define HDIM   64
#define MROWS  (BBATCH*TSEQ)

// Q scale: 1/sqrt(64) * log2(e)  (softmax in exp2 domain)
#define QSCALE 0.18033688011112042f

// Internal scratch (device globals: allocation-free rule). All half.
__device__ __half g_q[BBATCH*NHEAD*TSEQ*HDIM];   // [b,h,t,d], pre-scaled
__device__ __half g_k[BBATCH*NHEAD*TSEQ*HDIM];   // [b,h,t,d]
__device__ __half g_v[BBATCH*NHEAD*HDIM*TSEQ];   // [b,h,d,t]  (transposed!)
__device__ __half g_y[BBATCH*TSEQ*CDIM];         // attention out, half

__device__ __forceinline__ float ex2(float x){
    float r; asm("ex2.approx.f32 %0, %1;" : "=f"(r) : "f"(x)); return r;
}
__device__ __forceinline__ unsigned packh2(float a, float b){
    __half2 h = __floats2half2_rn(a, b); return *(unsigned*)&h;
}
__device__ __forceinline__ void mma_f16(float c[4],
    unsigned a0, unsigned a1, unsigned a2, unsigned a3,
    unsigned b0, unsigned b1)
{
    asm volatile(
        "mma.sync.aligned.m16n8k16.row.col.f32.f16.f16.f32 "
        "{%0,%1,%2,%3}, {%4,%5,%6,%7}, {%8,%9}, {%0,%1,%2,%3};"
        : "+f"(c[0]), "+f"(c[1]), "+f"(c[2]), "+f"(c[3])
        : "r"(a0), "r"(a1), "r"(a2), "r"(a3), "r"(b0), "r"(b1));
}
__device__ __forceinline__ void ldsm4(unsigned r[4], unsigned addr){
    asm volatile("ldmatrix.sync.aligned.m8n8.x4.shared.b16 {%0,%1,%2,%3}, [%4];"
        : "=r"(r[0]), "=r"(r[1]), "=r"(r[2]), "=r"(r[3]) : "r"(addr));
}
__device__ __forceinline__ void cpa16(void* dst, const void* src){
    unsigned d = (unsigned)__cvta_generic_to_shared(dst);
    asm volatile("cp.async.ca.shared.global [%0], [%1], 16;\n" :: "r"(d), "l"(src));
}
#define CP_COMMIT()  asm volatile("cp.async.commit_group;\n")
#define CP_WAIT(N)   asm volatile("cp.async.wait_group %0;\n" :: "n"(N))

// Per-lane ldmatrix source-row offsets.
//  A-type x4 (16x16 tile -> {a0,a1,a2,a3}): matrices rows{0-7,8-15} x cols{0,8}
//  B-type x4 (two 8-row n-blocks x cols{0,8} -> {b0,b1,b0',b1'})
__device__ __forceinline__ int lda_row(int lane){ return ((lane >> 3) & 1) * 8 + (lane & 7); }
__device__ __forceinline__ int lda_col(int lane){ return (lane >> 4) * 8; }
__device__ __forceinline__ int ldb_row(int lane){ return (lane >> 4) * 8 + (lane & 7); }
__device__ __forceinline__ int ldb_col(int lane){ return ((lane >> 3) & 1) * 8; }

// ---------------------------------------------------------------------------
// GEMM: out = A @ W^T + bias.  M=8192, N=512, K=512, fp16 mma, fp32 accum.
// Block 128x64, BK=32, 256 thr = 8 warps (4M x 2N), warp 32x32.
// Smem half, stride 40 halves (LDSM row bank 20r mod 32: conflict-free).
// MODE 0: ->g_q (scaled, half)  1: ->g_k (half)  2: ->g_v (half, TRANSPOSED)
// MODE 3: A = g_y (half), out = fp32 row-major.
// ---------------------------------------------------------------------------
#define GSTH 40

template<int MODE>
__global__ __launch_bounds__(256,2) void gemm_f16(
    const float* __restrict__ Ain, const float* __restrict__ W,
    const float* __restrict__ bias, float* __restrict__ outp)
{
    __shared__ __half sA[128*GSTH];
    __shared__ __half sB[64*GSTH];

    const int tid = threadIdx.x, lane = tid & 31, warp = tid >> 5;
    const int wm = warp >> 1, wn = warp & 1;
    const int g = lane >> 2, tig = lane & 3;
    const int m0 = blockIdx.y * 128, n0 = blockIdx.x * 64;

    const unsigned sAsh = (unsigned)__cvta_generic_to_shared(sA);
    const unsigned sBsh = (unsigned)__cvta_generic_to_shared(sB);
    const unsigned offA = (unsigned)((lda_row(lane)*GSTH + lda_col(lane)) * 2);
    const unsigned offB = (unsigned)((ldb_row(lane)*GSTH + ldb_col(lane)) * 2);

    float acc[2][4][4] = {};

    float4 ra[4]; uint4 rah[2]; float4 rb[2];
    if (MODE == 3) {
        #pragma unroll
        for (int l = 0; l < 2; l++) {
            int id = tid + l*256;                    // 128 rows x 4 chunks(8h)
            rah[l] = *(const uint4*)(g_y + (m0 + (id>>2))*CDIM + (id&3)*8);
        }
    } else {
        #pragma unroll
        for (int l = 0; l < 4; l++) {
            int id = tid + l*256;
            ra[l] = *(const float4*)(Ain + (m0 + (id>>3))*CDIM + ((id&7)<<2));
        }
    }
    #pragma unroll
    for (int l = 0; l < 2; l++) {
        int id = tid + l*256;
        rb[l] = *(const float4*)(W + (n0 + (id>>3))*CDIM + ((id&7)<<2));
    }

    for (int it = 0; it < 16; it++) {
        if (MODE == 3) {
            #pragma unroll
            for (int l = 0; l < 2; l++) {
                int id = tid + l*256;
                *(uint4*)&sA[(id>>2)*GSTH + (id&3)*8] = rah[l];
            }
        } else {
            #pragma unroll
            for (int l = 0; l < 4; l++) {
                int id = tid + l*256; int row = id>>3, kc = (id&7)<<2;
                *(uint2*)&sA[row*GSTH + kc] = make_uint2(
                    packh2(ra[l].x, ra[l].y), packh2(ra[l].z, ra[l].w));
            }
        }
        #pragma unroll
        for (int l = 0; l < 2; l++) {
            int id = tid + l*256; int row = id>>3, kc = (id&7)<<2;
            *(uint2*)&sB[row*GSTH + kc] = make_uint2(
                packh2(rb[l].x, rb[l].y), packh2(rb[l].z, rb[l].w));
        }
        __syncthreads();

        if (it < 15) {
            int kb = (it+1) * 32;
            if (MODE == 3) {
                #pragma unroll
                for (int l = 0; l < 2; l++) {
                    int id = tid + l*256;
                    rah[l] = *(const uint4*)(g_y + (m0 + (id>>2))*CDIM + kb + (id&3)*8);
                }
            } else {
                #pragma unroll
                for (int l = 0; l < 4; l++) {
                    int id = tid + l*256;
                    ra[l] = *(const float4*)(Ain + (m0 + (id>>3))*CDIM + kb + ((id&7)<<2));
                }
            }
            #pragma unroll
            for (int l = 0; l < 2; l++) {
                int id = tid + l*256;
                rb[l] = *(const float4*)(W + (n0 + (id>>3))*CDIM + kb + ((id&7)<<2));
            }
        }

        #pragma unroll
        for (int u = 0; u < 2; u++) {
            unsigned a[2][4], b[2][4];
            ldsm4(a[0], sAsh + (unsigned)(((wm*32      )*GSTH + 16*u)*2) + offA);
            ldsm4(a[1], sAsh + (unsigned)(((wm*32 + 16 )*GSTH + 16*u)*2) + offA);
            ldsm4(b[0], sBsh + (unsigned)(((wn*32      )*GSTH + 16*u)*2) + offB);
            ldsm4(b[1], sBsh + (unsigned)(((wn*32 + 16 )*GSTH + 16*u)*2) + offB);
            #pragma unroll
            for (int nt = 0; nt < 4; nt++) {
                unsigned b0 = b[nt>>1][(nt&1)*2], b1 = b[nt>>1][(nt&1)*2+1];
                mma_f16(acc[0][nt], a[0][0], a[0][1], a[0][2], a[0][3], b0, b1);
                mma_f16(acc[1][nt], a[1][0], a[1][1], a[1][2], a[1][3], b0, b1);
            }
        }
        __syncthreads();
    }

    #pragma unroll
    for (int mt = 0; mt < 2; mt++) {
        #pragma unroll
        for (int r = 0; r < 2; r++) {
            int row = m0 + wm*32 + mt*16 + g + r*8;
            #pragma unroll
            for (int nt = 0; nt < 4; nt++) {
                int col = n0 + wn*32 + nt*8 + tig*2;
                float2 bv = *(const float2*)(bias + col);
                float vx = acc[mt][nt][r*2+0] + bv.x;
                float vy = acc[mt][nt][r*2+1] + bv.y;
                if (MODE == 3) {
                    *(float2*)(outp + row*CDIM + col) = make_float2(vx, vy);
                } else {
                    int b = row >> 12, t = row & 4095, h = col >> 6, d = col & 63;
                    if (MODE == 0) { vx *= QSCALE; vy *= QSCALE; }
                    if (MODE == 2) {
                        // transposed: g_v[(bh*64 + d)*TSEQ + t]
                        __half* vp = g_v + (((b*NHEAD + h)*HDIM + d)*TSEQ) + t;
                        vp[0]    = __float2half_rn(vx);
                        vp[TSEQ] = __float2half_rn(vy);
                    } else {
                        __half* op = (MODE == 0) ? g_q : g_k;
                        *(unsigned*)&op[(((b*NHEAD + h)*TSEQ + t) << 6) + d] =
                            packh2(vx, vy);
                    }
                }
            }
        }
    }
}

// ---------------------------------------------------------------------------
// Flash attention, fp16 mma (m16n8k16), fp32 softmax/accum.
// Block = 128 q-rows x (b,h).  8 warps x 16 rows.  2 CTAs/SM.
// K [key][d] and V [d][key] (pre-transposed) in smem, stride 72 halves
// (LDSM row bank 4r mod 32: conflict-free).  cp.async double buffering.
// All fragment loads via ldmatrix.x4; P feeds PV directly from C-frags.
// ---------------------------------------------------------------------------
#define AST    72
#define STAGEH (64*AST*2)     // halves per stage (K tile + V tile) = 9216

__global__ __launch_bounds__(256,2) void attn_f16()
{
    extern __shared__ __half sm[];   // 2 stages = 18432 halves = 36864 B

    const int tid = threadIdx.x, lane = tid & 31, warp = tid >> 5;
    const int g = lane >> 2, tig = lane & 3;
    const int qi = (TSEQ/128 - 1) - blockIdx.x;     // big tiles first
    const int bh = blockIdx.y;
    const int q0 = qi * 128;
    const __half* __restrict__ Qp = g_q + bh*(TSEQ*HDIM);
    const __half* __restrict__ Kp = g_k + bh*(TSEQ*HDIM);
    const __half* __restrict__ Vp = g_v + bh*(HDIM*TSEQ);

    const unsigned smsh = (unsigned)__cvta_generic_to_shared(sm);
    const unsigned offA = (unsigned)((lda_row(lane)*AST + lda_col(lane)) * 2);
    const unsigned offB = (unsigned)((ldb_row(lane)*AST + ldb_col(lane)) * 2);

    // ---- stage Q into stage-0 (exactly one stage worth), load A-frags ----
    #pragma unroll
    for (int l = 0; l < 4; l++) {
        int id = tid + l*256; int row = id >> 3, c = id & 7;
        cpa16(sm + row*AST + c*8, Qp + ((q0 + row) << 6) + c*8);
    }
    CP_COMMIT();
    CP_WAIT(0);
    __syncthreads();

    unsigned qa[4][4];
    #pragma unroll
    for (int u = 0; u < 4; u++)
        ldsm4(qa[u], smsh + (unsigned)(((warp*16)*AST + 16*u)*2) + offA);
    __syncthreads();   // all warps done with Q before stage-0 overwrite

    const int nk = (q0 >> 6) + 2;

    auto copy_tile = [&](int kt, int s) {
        const int k0 = kt << 6;
        __half* Kd = sm + s*STAGEH;
        __half* Vd = Kd + 64*AST;
        #pragma unroll
        for (int l = 0; l < 2; l++) {
            int id = tid + l*256; int row = id >> 3, c = id & 7;
            cpa16(Kd + row*AST + c*8, Kp + ((k0 + row) << 6) + c*8);
        }
        #pragma unroll
        for (int l = 0; l < 2; l++) {
            int id = tid + l*256; int row = id >> 3, c = id & 7;
            cpa16(Vd + row*AST + c*8, Vp + row*TSEQ + k0 + c*8);
        }
        CP_COMMIT();
    };

    copy_tile(0, 0);

    float m0r = -1e30f, m1r = -1e30f, l0r = 0.f, l1r = 0.f;
    float O[8][4] = {};

    for (int kt = 0; kt < nk; kt++) {
        const int s = kt & 1;
        if (kt + 1 < nk) { copy_tile(kt + 1, s ^ 1); CP_WAIT(1); }
        else             { CP_WAIT(0); }
        __syncthreads();

        const unsigned Kb = smsh + (unsigned)(s*STAGEH*2);
        const unsigned Vb = Kb + (unsigned)(64*AST*2);

        // ---- S = Q K^T  (B-frags via ldmatrix: one x4 per key-pair per u) --
        float sc[8][4] = {};
        #pragma unroll
        for (int u = 0; u < 4; u++) {
            #pragma unroll
            for (int p = 0; p < 4; p++) {
                unsigned kb[4];
                ldsm4(kb, Kb + (unsigned)(((p*16)*AST + 16*u)*2) + offB);
                mma_f16(sc[2*p  ], qa[u][0], qa[u][1], qa[u][2], qa[u][3],
                        kb[0], kb[1]);
                mma_f16(sc[2*p+1], qa[u][0], qa[u][1], qa[u][2], qa[u][3],
                        kb[2], kb[3]);
            }
        }

        // ---- causal mask (last two tiles only) ----
        if (kt >= nk - 2) {
            int rbase = q0 + warp*16 + g;
            #pragma unroll
            for (int in = 0; in < 8; in++) {
                int cb = (kt << 6) + in*8 + tig*2;
                if (cb     > rbase)     sc[in][0] = -1e30f;
                if (cb + 1 > rbase)     sc[in][1] = -1e30f;
                if (cb     > rbase + 8) sc[in][2] = -1e30f;
                if (cb + 1 > rbase + 8) sc[in][3] = -1e30f;
            }
        }

        // ---- online softmax in exp2 domain (rows g, g+8; reduce over tig) --
        float mx0 = -1e30f, mx1 = -1e30f;
        #pragma unroll
        for (int in = 0; in < 8; in++) {
            mx0 = fmaxf(mx0, fmaxf(sc[in][0], sc[in][1]));
            mx1 = fmaxf(mx1, fmaxf(sc[in][2], sc[in][3]));
        }
        mx0 = fmaxf(mx0, __shfl_xor_sync(0xffffffffu, mx0, 1));
        mx0 = fmaxf(mx0, __shfl_xor_sync(0xffffffffu, mx0, 2));
        mx1 = fmaxf(mx1, __shfl_xor_sync(0xffffffffu, mx1, 1));
        mx1 = fmaxf(mx1, __shfl_xor_sync(0xffffffffu, mx1, 2));
        float mn0 = fmaxf(m0r, mx0), mn1 = fmaxf(m1r, mx1);
        float c0 = ex2(m0r - mn0), c1 = ex2(m1r - mn1);
        float s0 = 0.f, s1 = 0.f;
        #pragma unroll
        for (int in = 0; in < 8; in++) {
            sc[in][0] = ex2(sc[in][0] - mn0); s0 += sc[in][0];
            sc[in][1] = ex2(sc[in][1] - mn0); s0 += sc[in][1];
            sc[in][2] = ex2(sc[in][2] - mn1); s1 += sc[in][2];
            sc[in][3] = ex2(sc[in][3] - mn1); s1 += sc[in][3];
        }
        s0 += __shfl_xor_sync(0xffffffffu, s0, 1);
        s0 += __shfl_xor_sync(0xffffffffu, s0, 2);
        s1 += __shfl_xor_sync(0xffffffffu, s1, 1);
        s1 += __shfl_xor_sync(0xffffffffu, s1, 2);
        l0r = l0r*c0 + s0; l1r = l1r*c1 + s1;
        m0r = mn0; m1r = mn1;
        #pragma unroll
        for (int dn = 0; dn < 8; dn++) {
            O[dn][0] *= c0; O[dn][1] *= c0; O[dn][2] *= c1; O[dn][3] *= c1;
        }

        // ---- O += P V : pack C-frags straight into fp16 A-frags ----
        #pragma unroll
        for (int u = 0; u < 4; u++) {
            unsigned a0 = packh2(sc[2*u  ][0], sc[2*u  ][1]);
            unsigned a1 = packh2(sc[2*u  ][2], sc[2*u  ][3]);
            unsigned a2 = packh2(sc[2*u+1][0], sc[2*u+1][1]);
            unsigned a3 = packh2(sc[2*u+1][2], sc[2*u+1][3]);
            #pragma unroll
            for (int p = 0; p < 4; p++) {
                unsigned vb[4];
                ldsm4(vb, Vb + (unsigned)(((p*16)*AST + 16*u)*2) + offB);
                mma_f16(O[2*p  ], a0, a1, a2, a3, vb[0], vb[1]);
                mma_f16(O[2*p+1], a0, a1, a2, a3, vb[2], vb[3]);
            }
        }
        __syncthreads();   // stage s fully consumed before overwrite
    }

    // ---- epilogue: normalize, write half to g_y ----
    float i0 = 1.0f / l0r, i1 = 1.0f / l1r;
    int b = bh >> 3, h = bh & 7;
    int r0 = q0 + warp*16 + g;
    #pragma unroll
    for (int dn = 0; dn < 8; dn++) {
        int col = h*64 + dn*8 + tig*2;
        *(unsigned*)&g_y[(b*TSEQ + r0    )*CDIM + col] =
            packh2(O[dn][0]*i0, O[dn][1]*i0);
        *(unsigned*)&g_y[(b*TSEQ + r0 + 8)*CDIM + col] =
            packh2(O[dn][2]*i1, O[dn][3]*i1);
    }
}

// ---------------------------------------------------------------------------
// Inputs: x, weight, state, Wq, bq, Wk, bk, Wv, bv, Wp, bp
// ---------------------------------------------------------------------------
extern "C" void kernel_launch(void* const* d_in, const int* in_sizes, int n_in,
                              void* d_out, int out_size)
{
    (void)in_sizes; (void)n_in; (void)out_size;
    const float* x  = (const float*)d_in[0];
    const float* Wq = (const float*)d_in[3];
    const float* bq = (const float*)d_in[4];
    const float* Wk = (const float*)d_in[5];
    const float* bk = (const float*)d_in[6];
    const float* Wv = (const float*)d_in[7];
    const float* bv = (const float*)d_in[8];
    const float* Wp = (const float*)d_in[9];
    const float* bp = (const float*)d_in[10];
    float* out = (float*)d_out;

    dim3 gg(CDIM/64, MROWS/128);           // (8, 64)
    gemm_f16<0><<<gg, 256>>>(x, Wq, bq, nullptr);
    gemm_f16<1><<<gg, 256>>>(x, Wk, bk, nullptr);
    gemm_f16<2><<<gg, 256>>>(x, Wv, bv, nullptr);

    dim3 ga(TSEQ/128, BBATCH*NHEAD);       // (32, 16)
    attn_f16<<<ga, 256, STAGEH*2*sizeof(__half)>>>();

    gemm_f16<3><<<gg, 256>>>(nullptr, Wp, bp, out);
}

// round 12
// speedup vs baseline: 5.8425x; 1.0300x over previous
#include <cuda_runtime.h>
#include <cuda_fp16.h>
#include <cstdint>

#define BBATCH 2
#define TSEQ   4096
#define CDIM   512
#define NHEAD  8
#define HDIM   64
#define MROWS  (BBATCH*TSEQ)

// Q scale: 1/sqrt(64) * log2(e)  (softmax in exp2 domain)
#define QSCALE 0.18033688011112042f

// Internal scratch (device globals: allocation-free rule). All half.
__device__ __half g_q[BBATCH*NHEAD*TSEQ*HDIM];   // [b,h,t,d], pre-scaled
__device__ __half g_k[BBATCH*NHEAD*TSEQ*HDIM];   // [b,h,t,d]
__device__ __half g_v[BBATCH*NHEAD*HDIM*TSEQ];   // [b,h,d,t]  (transposed!)
__device__ __half g_y[BBATCH*TSEQ*CDIM];         // attention out, half

__device__ __forceinline__ float ex2(float x){
    float r; asm("ex2.approx.f32 %0, %1;" : "=f"(r) : "f"(x)); return r;
}
__device__ __forceinline__ unsigned packh2(float a, float b){
    __half2 h = __floats2half2_rn(a, b); return *(unsigned*)&h;
}
__device__ __forceinline__ void mma_f16(float c[4],
    unsigned a0, unsigned a1, unsigned a2, unsigned a3,
    unsigned b0, unsigned b1)
{
    asm volatile(
        "mma.sync.aligned.m16n8k16.row.col.f32.f16.f16.f32 "
        "{%0,%1,%2,%3}, {%4,%5,%6,%7}, {%8,%9}, {%0,%1,%2,%3};"
        : "+f"(c[0]), "+f"(c[1]), "+f"(c[2]), "+f"(c[3])
        : "r"(a0), "r"(a1), "r"(a2), "r"(a3), "r"(b0), "r"(b1));
}
__device__ __forceinline__ void ldsm4(unsigned r[4], unsigned addr){
    asm volatile("ldmatrix.sync.aligned.m8n8.x4.shared.b16 {%0,%1,%2,%3}, [%4];"
        : "=r"(r[0]), "=r"(r[1]), "=r"(r[2]), "=r"(r[3]) : "r"(addr));
}
__device__ __forceinline__ void cpa16(void* dst, const void* src){
    unsigned d = (unsigned)__cvta_generic_to_shared(dst);
    asm volatile("cp.async.ca.shared.global [%0], [%1], 16;\n" :: "r"(d), "l"(src));
}
#define CP_COMMIT()  asm volatile("cp.async.commit_group;\n")
#define CP_WAIT(N)   asm volatile("cp.async.wait_group %0;\n" :: "n"(N))

// Per-lane ldmatrix source offsets.
__device__ __forceinline__ int lda_row(int lane){ return ((lane >> 3) & 1) * 8 + (lane & 7); }
__device__ __forceinline__ int lda_col(int lane){ return (lane >> 4) * 8; }
__device__ __forceinline__ int ldb_row(int lane){ return (lane >> 4) * 8 + (lane & 7); }
__device__ __forceinline__ int ldb_col(int lane){ return ((lane >> 3) & 1) * 8; }

// ---------------------------------------------------------------------------
// QKV GEMM (one launch, z selects Q/K/V): out = x @ W^T + b, head-split store.
// Block 128x64, BK=32, 256 thr, fp16 mma fp32 accum, LDSM fragments.
// ---------------------------------------------------------------------------
#define GSTH 40

__global__ __launch_bounds__(256,2) void qkv_f16(
    const float* __restrict__ x,
    const float* __restrict__ Wq, const float* __restrict__ bq,
    const float* __restrict__ Wk, const float* __restrict__ bk,
    const float* __restrict__ Wv, const float* __restrict__ bv)
{
    __shared__ __half sA[128*GSTH];
    __shared__ __half sB[64*GSTH];

    const int z = blockIdx.z;
    const float* __restrict__ W    = (z == 0) ? Wq : (z == 1) ? Wk : Wv;
    const float* __restrict__ bias = (z == 0) ? bq : (z == 1) ? bk : bv;

    const int tid = threadIdx.x, lane = tid & 31, warp = tid >> 5;
    const int wm = warp >> 1, wn = warp & 1;
    const int g = lane >> 2, tig = lane & 3;
    const int m0 = blockIdx.y * 128, n0 = blockIdx.x * 64;

    const unsigned sAsh = (unsigned)__cvta_generic_to_shared(sA);
    const unsigned sBsh = (unsigned)__cvta_generic_to_shared(sB);
    const unsigned offA = (unsigned)((lda_row(lane)*GSTH + lda_col(lane)) * 2);
    const unsigned offB = (unsigned)((ldb_row(lane)*GSTH + ldb_col(lane)) * 2);

    float acc[2][4][4] = {};

    float4 ra[4], rb[2];
    #pragma unroll
    for (int l = 0; l < 4; l++) {
        int id = tid + l*256;
        ra[l] = *(const float4*)(x + (m0 + (id>>3))*CDIM + ((id&7)<<2));
    }
    #pragma unroll
    for (int l = 0; l < 2; l++) {
        int id = tid + l*256;
        rb[l] = *(const float4*)(W + (n0 + (id>>3))*CDIM + ((id&7)<<2));
    }

    for (int it = 0; it < 16; it++) {
        #pragma unroll
        for (int l = 0; l < 4; l++) {
            int id = tid + l*256; int row = id>>3, kc = (id&7)<<2;
            *(uint2*)&sA[row*GSTH + kc] = make_uint2(
                packh2(ra[l].x, ra[l].y), packh2(ra[l].z, ra[l].w));
        }
        #pragma unroll
        for (int l = 0; l < 2; l++) {
            int id = tid + l*256; int row = id>>3, kc = (id&7)<<2;
            *(uint2*)&sB[row*GSTH + kc] = make_uint2(
                packh2(rb[l].x, rb[l].y), packh2(rb[l].z, rb[l].w));
        }
        __syncthreads();

        if (it < 15) {
            int kb = (it+1) * 32;
            #pragma unroll
            for (int l = 0; l < 4; l++) {
                int id = tid + l*256;
                ra[l] = *(const float4*)(x + (m0 + (id>>3))*CDIM + kb + ((id&7)<<2));
            }
            #pragma unroll
            for (int l = 0; l < 2; l++) {
                int id = tid + l*256;
                rb[l] = *(const float4*)(W + (n0 + (id>>3))*CDIM + kb + ((id&7)<<2));
            }
        }

        #pragma unroll
        for (int u = 0; u < 2; u++) {
            unsigned a[2][4], b[2][4];
            ldsm4(a[0], sAsh + (unsigned)(((wm*32      )*GSTH + 16*u)*2) + offA);
            ldsm4(a[1], sAsh + (unsigned)(((wm*32 + 16 )*GSTH + 16*u)*2) + offA);
            ldsm4(b[0], sBsh + (unsigned)(((wn*32      )*GSTH + 16*u)*2) + offB);
            ldsm4(b[1], sBsh + (unsigned)(((wn*32 + 16 )*GSTH + 16*u)*2) + offB);
            #pragma unroll
            for (int nt = 0; nt < 4; nt++) {
                unsigned b0 = b[nt>>1][(nt&1)*2], b1 = b[nt>>1][(nt&1)*2+1];
                mma_f16(acc[0][nt], a[0][0], a[0][1], a[0][2], a[0][3], b0, b1);
                mma_f16(acc[1][nt], a[1][0], a[1][1], a[1][2], a[1][3], b0, b1);
            }
        }
        __syncthreads();
    }

    #pragma unroll
    for (int mt = 0; mt < 2; mt++) {
        #pragma unroll
        for (int r = 0; r < 2; r++) {
            int row = m0 + wm*32 + mt*16 + g + r*8;
            #pragma unroll
            for (int nt = 0; nt < 4; nt++) {
                int col = n0 + wn*32 + nt*8 + tig*2;
                float2 bv = *(const float2*)(bias + col);
                float vx = acc[mt][nt][r*2+0] + bv.x;
                float vy = acc[mt][nt][r*2+1] + bv.y;
                int b = row >> 12, t = row & 4095, h = col >> 6, d = col & 63;
                if (z == 0) {
                    vx *= QSCALE; vy *= QSCALE;
                    *(unsigned*)&g_q[(((b*NHEAD + h)*TSEQ + t) << 6) + d] =
                        packh2(vx, vy);
                } else if (z == 1) {
                    *(unsigned*)&g_k[(((b*NHEAD + h)*TSEQ + t) << 6) + d] =
                        packh2(vx, vy);
                } else {
                    __half* vp = g_v + (((b*NHEAD + h)*HDIM + d)*TSEQ) + t;
                    vp[0]    = __float2half_rn(vx);
                    vp[TSEQ] = __float2half_rn(vy);
                }
            }
        }
    }
}

// ---------------------------------------------------------------------------
// Output projection: out(fp32) = g_y(half) @ Wp^T + bp.
// ---------------------------------------------------------------------------
__global__ __launch_bounds__(256,2) void proj_f16(
    const float* __restrict__ W, const float* __restrict__ bias,
    float* __restrict__ outp)
{
    __shared__ __half sA[128*GSTH];
    __shared__ __half sB[64*GSTH];

    const int tid = threadIdx.x, lane = tid & 31, warp = tid >> 5;
    const int wm = warp >> 1, wn = warp & 1;
    const int g = lane >> 2, tig = lane & 3;
    const int m0 = blockIdx.y * 128, n0 = blockIdx.x * 64;

    const unsigned sAsh = (unsigned)__cvta_generic_to_shared(sA);
    const unsigned sBsh = (unsigned)__cvta_generic_to_shared(sB);
    const unsigned offA = (unsigned)((lda_row(lane)*GSTH + lda_col(lane)) * 2);
    const unsigned offB = (unsigned)((ldb_row(lane)*GSTH + ldb_col(lane)) * 2);

    float acc[2][4][4] = {};

    uint4 rah[2]; float4 rb[2];
    #pragma unroll
    for (int l = 0; l < 2; l++) {
        int id = tid + l*256;
        rah[l] = *(const uint4*)(g_y + (m0 + (id>>2))*CDIM + (id&3)*8);
    }
    #pragma unroll
    for (int l = 0; l < 2; l++) {
        int id = tid + l*256;
        rb[l] = *(const float4*)(W + (n0 + (id>>3))*CDIM + ((id&7)<<2));
    }

    for (int it = 0; it < 16; it++) {
        #pragma unroll
        for (int l = 0; l < 2; l++) {
            int id = tid + l*256;
            *(uint4*)&sA[(id>>2)*GSTH + (id&3)*8] = rah[l];
        }
        #pragma unroll
        for (int l = 0; l < 2; l++) {
            int id = tid + l*256; int row = id>>3, kc = (id&7)<<2;
            *(uint2*)&sB[row*GSTH + kc] = make_uint2(
                packh2(rb[l].x, rb[l].y), packh2(rb[l].z, rb[l].w));
        }
        __syncthreads();

        if (it < 15) {
            int kb = (it+1) * 32;
            #pragma unroll
            for (int l = 0; l < 2; l++) {
                int id = tid + l*256;
                rah[l] = *(const uint4*)(g_y + (m0 + (id>>2))*CDIM + kb + (id&3)*8);
            }
            #pragma unroll
            for (int l = 0; l < 2; l++) {
                int id = tid + l*256;
                rb[l] = *(const float4*)(W + (n0 + (id>>3))*CDIM + kb + ((id&7)<<2));
            }
        }

        #pragma unroll
        for (int u = 0; u < 2; u++) {
            unsigned a[2][4], b[2][4];
            ldsm4(a[0], sAsh + (unsigned)(((wm*32      )*GSTH + 16*u)*2) + offA);
            ldsm4(a[1], sAsh + (unsigned)(((wm*32 + 16 )*GSTH + 16*u)*2) + offA);
            ldsm4(b[0], sBsh + (unsigned)(((wn*32      )*GSTH + 16*u)*2) + offB);
            ldsm4(b[1], sBsh + (unsigned)(((wn*32 + 16 )*GSTH + 16*u)*2) + offB);
            #pragma unroll
            for (int nt = 0; nt < 4; nt++) {
                unsigned b0 = b[nt>>1][(nt&1)*2], b1 = b[nt>>1][(nt&1)*2+1];
                mma_f16(acc[0][nt], a[0][0], a[0][1], a[0][2], a[0][3], b0, b1);
                mma_f16(acc[1][nt], a[1][0], a[1][1], a[1][2], a[1][3], b0, b1);
            }
        }
        __syncthreads();
    }

    #pragma unroll
    for (int mt = 0; mt < 2; mt++) {
        #pragma unroll
        for (int r = 0; r < 2; r++) {
            int row = m0 + wm*32 + mt*16 + g + r*8;
            #pragma unroll
            for (int nt = 0; nt < 4; nt++) {
                int col = n0 + wn*32 + nt*8 + tig*2;
                float2 bv = *(const float2*)(bias + col);
                *(float2*)(outp + row*CDIM + col) = make_float2(
                    acc[mt][nt][r*2+0] + bv.x, acc[mt][nt][r*2+1] + bv.y);
            }
        }
    }
}

// ---------------------------------------------------------------------------
// Flash attention, fp16 mma.  Block = 128 q-rows x (b,h).  8 warps, 2 CTAs/SM.
// KT=128 stages (two 64-key sub-tiles), single __syncthreads per stage.
// K [key][d] stride 72; V [d][key] stride 136 (both conflict-free for LDSM).
// cp.async double buffering; copy issued AFTER the stage barrier.
// ---------------------------------------------------------------------------
#define AST    72
#define VST    136
#define KTILEH (128*AST)              // 9216 halves
#define STAGEH (KTILEH + 64*VST)      // 17920 halves = 35840 B

__global__ __launch_bounds__(256,2) void attn_f16()
{
    extern __shared__ __half sm[];   // 2 stages = 71680 B

    const int tid = threadIdx.x, lane = tid & 31, warp = tid >> 5;
    const int g = lane >> 2, tig = lane & 3;
    const int qi = (TSEQ/128 - 1) - blockIdx.x;     // big tiles first
    const int bh = blockIdx.y;
    const int q0 = qi * 128;
    const __half* __restrict__ Qp = g_q + bh*(TSEQ*HDIM);
    const __half* __restrict__ Kp = g_k + bh*(TSEQ*HDIM);
    const __half* __restrict__ Vp = g_v + bh*(HDIM*TSEQ);

    const unsigned smsh = (unsigned)__cvta_generic_to_shared(sm);
    const unsigned offA = (unsigned)((lda_row(lane)*AST + lda_col(lane)) * 2);
    const unsigned offBK = (unsigned)((ldb_row(lane)*AST + ldb_col(lane)) * 2);
    const unsigned offBV = (unsigned)((ldb_row(lane)*VST + ldb_col(lane)) * 2);

    // ---- stage Q into stage-0 K region, load A-frags ----
    #pragma unroll
    for (int l = 0; l < 4; l++) {
        int id = tid + l*256; int row = id >> 3, c = id & 7;
        cpa16(sm + row*AST + c*8, Qp + ((q0 + row) << 6) + c*8);
    }
    CP_COMMIT();
    CP_WAIT(0);
    __syncthreads();

    unsigned qa[4][4];
    #pragma unroll
    for (int u = 0; u < 4; u++)
        ldsm4(qa[u], smsh + (unsigned)(((warp*16)*AST + 16*u)*2) + offA);
    __syncthreads();   // all warps done with Q before stage-0 overwrite

    const int nst  = qi + 1;          // 128-key stages
    const int nk64 = 2*qi + 2;        // 64-key sub-tiles

    auto copy_stage = [&](int st, int s) {
        const int k0 = st << 7;
        __half* Kd = sm + s*STAGEH;
        __half* Vd = Kd + KTILEH;
        #pragma unroll
        for (int l = 0; l < 4; l++) {
            int id = tid + l*256; int row = id >> 3, c = id & 7;
            cpa16(Kd + row*AST + c*8, Kp + ((k0 + row) << 6) + c*8);
        }
        #pragma unroll
        for (int l = 0; l < 4; l++) {
            int id = tid + l*256; int row = id >> 4, c = id & 15;
            cpa16(Vd + row*VST + c*8, Vp + row*TSEQ + k0 + c*8);
        }
        CP_COMMIT();
    };

    copy_stage(0, 0);

    float m0r = -1e30f, m1r = -1e30f, l0r = 0.f, l1r = 0.f;
    float O[8][4] = {};

    for (int st = 0; st < nst; st++) {
        const int s = st & 1;
        CP_WAIT(0);
        __syncthreads();              // stage s ready; stage s^1 reads done
        if (st + 1 < nst) copy_stage(st + 1, s ^ 1);

        const unsigned Kb = smsh + (unsigned)(s*STAGEH*2);
        const unsigned Vb = Kb + (unsigned)(KTILEH*2);

        #pragma unroll
        for (int sub = 0; sub < 2; sub++) {
            const int kk = 2*st + sub;            // 64-key tile index
            const unsigned Ksub = Kb + (unsigned)(sub*64*AST*2);
            const unsigned Vsub = Vb + (unsigned)(sub*64*2);

            // ---- S = Q K^T ----
            float sc[8][4] = {};
            #pragma unroll
            for (int u = 0; u < 4; u++) {
                #pragma unroll
                for (int p = 0; p < 4; p++) {
                    unsigned kb[4];
                    ldsm4(kb, Ksub + (unsigned)(((p*16)*AST + 16*u)*2) + offBK);
                    mma_f16(sc[2*p  ], qa[u][0], qa[u][1], qa[u][2], qa[u][3],
                            kb[0], kb[1]);
                    mma_f16(sc[2*p+1], qa[u][0], qa[u][1], qa[u][2], qa[u][3],
                            kb[2], kb[3]);
                }
            }

            // ---- causal mask (last two 64-key tiles only) ----
            if (kk >= nk64 - 2) {
                int rbase = q0 + warp*16 + g;
                #pragma unroll
                for (int in = 0; in < 8; in++) {
                    int cb = (kk << 6) + in*8 + tig*2;
                    if (cb     > rbase)     sc[in][0] = -1e30f;
                    if (cb + 1 > rbase)     sc[in][1] = -1e30f;
                    if (cb     > rbase + 8) sc[in][2] = -1e30f;
                    if (cb + 1 > rbase + 8) sc[in][3] = -1e30f;
                }
            }

            // ---- online softmax (exp2 domain) ----
            float mx0 = -1e30f, mx1 = -1e30f;
            #pragma unroll
            for (int in = 0; in < 8; in++) {
                mx0 = fmaxf(mx0, fmaxf(sc[in][0], sc[in][1]));
                mx1 = fmaxf(mx1, fmaxf(sc[in][2], sc[in][3]));
            }
            mx0 = fmaxf(mx0, __shfl_xor_sync(0xffffffffu, mx0, 1));
            mx0 = fmaxf(mx0, __shfl_xor_sync(0xffffffffu, mx0, 2));
            mx1 = fmaxf(mx1, __shfl_xor_sync(0xffffffffu, mx1, 1));
            mx1 = fmaxf(mx1, __shfl_xor_sync(0xffffffffu, mx1, 2));
            float mn0 = fmaxf(m0r, mx0), mn1 = fmaxf(m1r, mx1);
            float c0 = ex2(m0r - mn0), c1 = ex2(m1r - mn1);
            float s0 = 0.f, s1 = 0.f;
            #pragma unroll
            for (int in = 0; in < 8; in++) {
                sc[in][0] = ex2(sc[in][0] - mn0); s0 += sc[in][0];
                sc[in][1] = ex2(sc[in][1] - mn0); s0 += sc[in][1];
                sc[in][2] = ex2(sc[in][2] - mn1); s1 += sc[in][2];
                sc[in][3] = ex2(sc[in][3] - mn1); s1 += sc[in][3];
            }
            s0 += __shfl_xor_sync(0xffffffffu, s0, 1);
            s0 += __shfl_xor_sync(0xffffffffu, s0, 2);
            s1 += __shfl_xor_sync(0xffffffffu, s1, 1);
            s1 += __shfl_xor_sync(0xffffffffu, s1, 2);
            l0r = l0r*c0 + s0; l1r = l1r*c1 + s1;
            m0r = mn0; m1r = mn1;

            // skip rescale when max unchanged for the whole warp (c==1 exact)
            if (!__all_sync(0xffffffffu, (c0 == 1.0f) && (c1 == 1.0f))) {
                #pragma unroll
                for (int dn = 0; dn < 8; dn++) {
                    O[dn][0] *= c0; O[dn][1] *= c0;
                    O[dn][2] *= c1; O[dn][3] *= c1;
                }
            }

            // ---- O += P V ----
            #pragma unroll
            for (int u = 0; u < 4; u++) {
                unsigned a0 = packh2(sc[2*u  ][0], sc[2*u  ][1]);
                unsigned a1 = packh2(sc[2*u  ][2], sc[2*u  ][3]);
                unsigned a2 = packh2(sc[2*u+1][0], sc[2*u+1][1]);
                unsigned a3 = packh2(sc[2*u+1][2], sc[2*u+1][3]);
                #pragma unroll
                for (int p = 0; p < 4; p++) {
                    unsigned vb[4];
                    ldsm4(vb, Vsub + (unsigned)(((p*16)*VST + 16*u)*2) + offBV);
                    mma_f16(O[2*p  ], a0, a1, a2, a3, vb[0], vb[1]);
                    mma_f16(O[2*p+1], a0, a1, a2, a3, vb[2], vb[3]);
                }
            }
        }
    }

    // ---- epilogue: normalize, write half to g_y ----
    float i0 = 1.0f / l0r, i1 = 1.0f / l1r;
    int b = bh >> 3, h = bh & 7;
    int r0 = q0 + warp*16 + g;
    #pragma unroll
    for (int dn = 0; dn < 8; dn++) {
        int col = h*64 + dn*8 + tig*2;
        *(unsigned*)&g_y[(b*TSEQ + r0    )*CDIM + col] =
            packh2(O[dn][0]*i0, O[dn][1]*i0);
        *(unsigned*)&g_y[(b*TSEQ + r0 + 8)*CDIM + col] =
            packh2(O[dn][2]*i1, O[dn][3]*i1);
    }
}

// ---------------------------------------------------------------------------
// Inputs: x, weight, state, Wq, bq, Wk, bk, Wv, bv, Wp, bp
// ---------------------------------------------------------------------------
extern "C" void kernel_launch(void* const* d_in, const int* in_sizes, int n_in,
                              void* d_out, int out_size)
{
    (void)in_sizes; (void)n_in; (void)out_size;
    const float* x  = (const float*)d_in[0];
    const float* Wq = (const float*)d_in[3];
    const float* bq = (const float*)d_in[4];
    const float* Wk = (const float*)d_in[5];
    const float* bk = (const float*)d_in[6];
    const float* Wv = (const float*)d_in[7];
    const float* bv = (const float*)d_in[8];
    const float* Wp = (const float*)d_in[9];
    const float* bp = (const float*)d_in[10];
    float* out = (float*)d_out;

    static bool attr_done = false;
    if (!attr_done) {
        cudaFuncSetAttribute(attn_f16,
            cudaFuncAttributeMaxDynamicSharedMemorySize, STAGEH*2*sizeof(__half));
        attr_done = true;
    }

    dim3 gqkv(CDIM/64, MROWS/128, 3);      // (8, 64, 3)
    qkv_f16<<<gqkv, 256>>>(x, Wq, bq, Wk, bk, Wv, bv);

    dim3 ga(TSEQ/128, BBATCH*NHEAD);       // (32, 16)
    attn_f16<<<ga, 256, STAGEH*2*sizeof(__half)>>>();

    dim3 gp(CDIM/64, MROWS/128);           // (8, 64)
    proj_f16<<<gp, 256>>>(Wp, bp, out);
}

// round 14
// speedup vs baseline: 6.3700x; 1.0903x over previous
#include <cuda_runtime.h>
#include <cuda_fp16.h>
#include <cstdint>

#define BBATCH 2
#define TSEQ   4096
#define CDIM   512
#define NHEAD  8
#define HDIM   64
#define MROWS  (BBATCH*TSEQ)

// Q scale: 1/sqrt(64) * log2(e)  (softmax in exp2 domain)
#define QSCALE 0.18033688011112042f

// Internal scratch (device globals: allocation-free rule). All half.
__device__ __half g_xh[MROWS*CDIM];              // x converted to half
__device__ __half g_wh[4*CDIM*CDIM];             // Wq,Wk,Wv,Wp in half
__device__ __half g_q[BBATCH*NHEAD*TSEQ*HDIM];   // [b,h,t,d], pre-scaled
__device__ __half g_k[BBATCH*NHEAD*TSEQ*HDIM];   // [b,h,t,d]
__device__ __half g_v[BBATCH*NHEAD*HDIM*TSEQ];   // [b,h,d,t]  (transposed!)
__device__ __half g_y[BBATCH*TSEQ*CDIM];         // attention out, half

__device__ __forceinline__ float ex2(float x){
    float r; asm("ex2.approx.f32 %0, %1;" : "=f"(r) : "f"(x)); return r;
}
__device__ __forceinline__ unsigned packh2(float a, float b){
    __half2 h = __floats2half2_rn(a, b); return *(unsigned*)&h;
}
__device__ __forceinline__ void mma_f16(float c[4],
    unsigned a0, unsigned a1, unsigned a2, unsigned a3,
    unsigned b0, unsigned b1)
{
    asm volatile(
        "mma.sync.aligned.m16n8k16.row.col.f32.f16.f16.f32 "
        "{%0,%1,%2,%3}, {%4,%5,%6,%7}, {%8,%9}, {%0,%1,%2,%3};"
        : "+f"(c[0]), "+f"(c[1]), "+f"(c[2]), "+f"(c[3])
        : "r"(a0), "r"(a1), "r"(a2), "r"(a3), "r"(b0), "r"(b1));
}
__device__ __forceinline__ void ldsm4(unsigned r[4], unsigned addr){
    asm volatile("ldmatrix.sync.aligned.m8n8.x4.shared.b16 {%0,%1,%2,%3}, [%4];"
        : "=r"(r[0]), "=r"(r[1]), "=r"(r[2]), "=r"(r[3]) : "r"(addr));
}
__device__ __forceinline__ void cpa16(void* dst, const void* src){
    unsigned d = (unsigned)__cvta_generic_to_shared(dst);
    asm volatile("cp.async.ca.shared.global [%0], [%1], 16;\n" :: "r"(d), "l"(src));
}
#define CP_COMMIT()  asm volatile("cp.async.commit_group;\n")
#define CP_WAIT(N)   asm volatile("cp.async.wait_group %0;\n" :: "n"(N))

// Per-lane ldmatrix source offsets.
__device__ __forceinline__ int lda_row(int lane){ return ((lane >> 3) & 1) * 8 + (lane & 7); }
__device__ __forceinline__ int lda_col(int lane){ return (lane >> 4) * 8; }
__device__ __forceinline__ int ldb_row(int lane){ return (lane >> 4) * 8 + (lane & 7); }
__device__ __forceinline__ int ldb_col(int lane){ return ((lane >> 3) & 1) * 8; }

// ---------------------------------------------------------------------------
// fp32 -> fp16 conversion (x and the four weight matrices)
// ---------------------------------------------------------------------------
__global__ __launch_bounds__(256,8) void cvt_f2h(
    const float* __restrict__ src, __half* __restrict__ dst)
{
    int i = (blockIdx.x*256 + threadIdx.x) * 4;
    float4 v = *(const float4*)(src + i);
    *(uint2*)(dst + i) = make_uint2(packh2(v.x, v.y), packh2(v.z, v.w));
}

// ---------------------------------------------------------------------------
// GEMM core: out = A @ W^T + bias.  A,W already half in gmem.
// Block 128x64, BK=64, 256 thr = 8 warps (4M x 2N).
// 3-stage cp.async pipeline, ONE barrier per iteration, LDSM fragments.
// Smem stride 72 halves (LDSM row bank 4r mod 32: conflict-free).
// ---------------------------------------------------------------------------
#define GAST 72
#define GASTG (128*GAST)             // A tile halves
#define GBSTG (64*GAST)              // B tile halves
#define GSTG  (GASTG + GBSTG)        // 13824 halves = 27648 B / stage

template<bool QKV>
__global__ __launch_bounds__(256,2) void gemm_h(
    const float* __restrict__ bias_q, const float* __restrict__ bias_k,
    const float* __restrict__ bias_v, float* __restrict__ outp)
{
    extern __shared__ __half gs[];   // 3 stages

    const int z = QKV ? blockIdx.z : 3;
    const __half* __restrict__ A = QKV ? g_xh : g_y;
    const __half* __restrict__ W = g_wh + z*(CDIM*CDIM);
    const float* __restrict__ bias =
        (z == 0) ? bias_q : (z == 1) ? bias_k : (z == 2) ? bias_v : bias_q;

    const int tid = threadIdx.x, lane = tid & 31, warp = tid >> 5;
    const int wm = warp >> 1, wn = warp & 1;
    const int g = lane >> 2, tig = lane & 3;
    const int m0 = blockIdx.y * 128, n0 = blockIdx.x * 64;

    const unsigned smsh = (unsigned)__cvta_generic_to_shared(gs);
    const unsigned offA = (unsigned)((lda_row(lane)*GAST + lda_col(lane)) * 2);
    const unsigned offB = (unsigned)((ldb_row(lane)*GAST + ldb_col(lane)) * 2);

    auto copy_stage = [&](int it, int s) {
        const int k0 = it << 6;
        __half* Ad = gs + s*GSTG;
        __half* Bd = Ad + GASTG;
        #pragma unroll
        for (int l = 0; l < 4; l++) {
            int id = tid + l*256; int row = id >> 3, c = id & 7;
            cpa16(Ad + row*GAST + c*8, A + (m0 + row)*CDIM + k0 + c*8);
        }
        #pragma unroll
        for (int l = 0; l < 2; l++) {
            int id = tid + l*256; int row = id >> 3, c = id & 7;
            cpa16(Bd + row*GAST + c*8, W + (n0 + row)*CDIM + k0 + c*8);
        }
        CP_COMMIT();
    };

    copy_stage(0, 0);
    copy_stage(1, 1);

    float acc[2][4][4] = {};

    for (int it = 0; it < 8; it++) {
        const int s = it % 3;
        CP_WAIT(1);
        __syncthreads();                       // stage s ready; (it-1)%3 free
        if (it + 2 < 8) copy_stage(it + 2, (it + 2) % 3);

        const unsigned Ab = smsh + (unsigned)(s*GSTG*2);
        const unsigned Bb = Ab + (unsigned)(GASTG*2);

        #pragma unroll
        for (int u = 0; u < 4; u++) {
            unsigned a[2][4], b[2][4];
            ldsm4(a[0], Ab + (unsigned)(((wm*32      )*GAST + 16*u)*2) + offA);
            ldsm4(a[1], Ab + (unsigned)(((wm*32 + 16 )*GAST + 16*u)*2) + offA);
            ldsm4(b[0], Bb + (unsigned)(((wn*32      )*GAST + 16*u)*2) + offB);
            ldsm4(b[1], Bb + (unsigned)(((wn*32 + 16 )*GAST + 16*u)*2) + offB);
            #pragma unroll
            for (int nt = 0; nt < 4; nt++) {
                unsigned b0 = b[nt>>1][(nt&1)*2], b1 = b[nt>>1][(nt&1)*2+1];
                mma_f16(acc[0][nt], a[0][0], a[0][1], a[0][2], a[0][3], b0, b1);
                mma_f16(acc[1][nt], a[1][0], a[1][1], a[1][2], a[1][3], b0, b1);
            }
        }
    }

    #pragma unroll
    for (int mt = 0; mt < 2; mt++) {
        #pragma unroll
        for (int r = 0; r < 2; r++) {
            int row = m0 + wm*32 + mt*16 + g + r*8;
            #pragma unroll
            for (int nt = 0; nt < 4; nt++) {
                int col = n0 + wn*32 + nt*8 + tig*2;
                float2 bv = *(const float2*)(bias + col);
                float vx = acc[mt][nt][r*2+0] + bv.x;
                float vy = acc[mt][nt][r*2+1] + bv.y;
                if (!QKV) {
                    *(float2*)(outp + row*CDIM + col) = make_float2(vx, vy);
                } else {
                    int b = row >> 12, t = row & 4095, h = col >> 6, d = col & 63;
                    if (z == 0) {
                        vx *= QSCALE; vy *= QSCALE;
                        *(unsigned*)&g_q[(((b*NHEAD + h)*TSEQ + t) << 6) + d] =
                            packh2(vx, vy);
                    } else if (z == 1) {
                        *(unsigned*)&g_k[(((b*NHEAD + h)*TSEQ + t) << 6) + d] =
                            packh2(vx, vy);
                    } else {
                        __half* vp = g_v + (((b*NHEAD + h)*HDIM + d)*TSEQ) + t;
                        vp[0]    = __float2half_rn(vx);
                        vp[TSEQ] = __float2half_rn(vy);
                    }
                }
            }
        }
    }
}

// ---------------------------------------------------------------------------
// Flash attention, fp16 mma.  Block = 128 q-rows x (b,h).  8 warps, 2 CTAs/SM.
// KT=128 stages (two 64-key sub-tiles), single __syncthreads per stage.
// K [key][d] stride 72; V [d][key] stride 136 (both conflict-free for LDSM).
// cp.async double buffering; copy issued AFTER the stage barrier.
// ---------------------------------------------------------------------------
#define AST    72
#define VST    136
#define KTILEH (128*AST)              // 9216 halves
#define STAGEH (KTILEH + 64*VST)      // 17920 halves = 35840 B

__global__ __launch_bounds__(256,2) void attn_f16()
{
    extern __shared__ __half sm[];   // 2 stages = 71680 B

    const int tid = threadIdx.x, lane = tid & 31, warp = tid >> 5;
    const int g = lane >> 2, tig = lane & 3;
    const int qi = (TSEQ/128 - 1) - blockIdx.x;     // big tiles first
    const int bh = blockIdx.y;
    const int q0 = qi * 128;
    const __half* __restrict__ Qp = g_q + bh*(TSEQ*HDIM);
    const __half* __restrict__ Kp = g_k + bh*(TSEQ*HDIM);
    const __half* __restrict__ Vp = g_v + bh*(HDIM*TSEQ);

    const unsigned smsh = (unsigned)__cvta_generic_to_shared(sm);
    const unsigned offA = (unsigned)((lda_row(lane)*AST + lda_col(lane)) * 2);
    const unsigned offBK = (unsigned)((ldb_row(lane)*AST + ldb_col(lane)) * 2);
    const unsigned offBV = (unsigned)((ldb_row(lane)*VST + ldb_col(lane)) * 2);

    // ---- stage Q into stage-0 K region, load A-frags ----
    #pragma unroll
    for (int l = 0; l < 4; l++) {
        int id = tid + l*256; int row = id >> 3, c = id & 7;
        cpa16(sm + row*AST + c*8, Qp + ((q0 + row) << 6) + c*8);
    }
    CP_COMMIT();
    CP_WAIT(0);
    __syncthreads();

    unsigned qa[4][4];
    #pragma unroll
    for (int u = 0; u < 4; u++)
        ldsm4(qa[u], smsh + (unsigned)(((warp*16)*AST + 16*u)*2) + offA);
    __syncthreads();   // all warps done with Q before stage-0 overwrite

    const int nst  = qi + 1;          // 128-key stages
    const int nk64 = 2*qi + 2;        // 64-key sub-tiles

    auto copy_stage = [&](int st, int s) {
        const int k0 = st << 7;
        __half* Kd = sm + s*STAGEH;
        __half* Vd = Kd + KTILEH;
        #pragma unroll
        for (int l = 0; l < 4; l++) {
            int id = tid + l*256; int row = id >> 3, c = id & 7;
            cpa16(Kd + row*AST + c*8, Kp + ((k0 + row) << 6) + c*8);
        }
        #pragma unroll
        for (int l = 0; l < 4; l++) {
            int id = tid + l*256; int row = id >> 4, c = id & 15;
            cpa16(Vd + row*VST + c*8, Vp + row*TSEQ + k0 + c*8);
        }
        CP_COMMIT();
    };

    copy_stage(0, 0);

    float m0r = -1e30f, m1r = -1e30f, l0r = 0.f, l1r = 0.f;
    float O[8][4] = {};

    for (int st = 0; st < nst; st++) {
        const int s = st & 1;
        CP_WAIT(0);
        __syncthreads();              // stage s ready; stage s^1 reads done
        if (st + 1 < nst) copy_stage(st + 1, s ^ 1);

        const unsigned Kb = smsh + (unsigned)(s*STAGEH*2);
        const unsigned Vb = Kb + (unsigned)(KTILEH*2);

        #pragma unroll
        for (int sub = 0; sub < 2; sub++) {
            const int kk = 2*st + sub;            // 64-key tile index
            const unsigned Ksub = Kb + (unsigned)(sub*64*AST*2);
            const unsigned Vsub = Vb + (unsigned)(sub*64*2);

            // ---- S = Q K^T ----
            float sc[8][4] = {};
            #pragma unroll
            for (int u = 0; u < 4; u++) {
                #pragma unroll
                for (int p = 0; p < 4; p++) {
                    unsigned kb[4];
                    ldsm4(kb, Ksub + (unsigned)(((p*16)*AST + 16*u)*2) + offBK);
                    mma_f16(sc[2*p  ], qa[u][0], qa[u][1], qa[u][2], qa[u][3],
                            kb[0], kb[1]);
                    mma_f16(sc[2*p+1], qa[u][0], qa[u][1], qa[u][2], qa[u][3],
                            kb[2], kb[3]);
                }
            }

            // ---- causal mask (last two 64-key tiles only) ----
            if (kk >= nk64 - 2) {
                int rbase = q0 + warp*16 + g;
                #pragma unroll
                for (int in = 0; in < 8; in++) {
                    int cb = (kk << 6) + in*8 + tig*2;
                    if (cb     > rbase)     sc[in][0] = -1e30f;
                    if (cb + 1 > rbase)     sc[in][1] = -1e30f;
                    if (cb     > rbase + 8) sc[in][2] = -1e30f;
                    if (cb + 1 > rbase + 8) sc[in][3] = -1e30f;
                }
            }

            // ---- online softmax (exp2 domain) ----
            float mx0 = -1e30f, mx1 = -1e30f;
            #pragma unroll
            for (int in = 0; in < 8; in++) {
                mx0 = fmaxf(mx0, fmaxf(sc[in][0], sc[in][1]));
                mx1 = fmaxf(mx1, fmaxf(sc[in][2], sc[in][3]));
            }
            mx0 = fmaxf(mx0, __shfl_xor_sync(0xffffffffu, mx0, 1));
            mx0 = fmaxf(mx0, __shfl_xor_sync(0xffffffffu, mx0, 2));
            mx1 = fmaxf(mx1, __shfl_xor_sync(0xffffffffu, mx1, 1));
            mx1 = fmaxf(mx1, __shfl_xor_sync(0xffffffffu, mx1, 2));
            float mn0 = fmaxf(m0r, mx0), mn1 = fmaxf(m1r, mx1);
            float c0 = ex2(m0r - mn0), c1 = ex2(m1r - mn1);
            float s0 = 0.f, s1 = 0.f;
            #pragma unroll
            for (int in = 0; in < 8; in++) {
                sc[in][0] = ex2(sc[in][0] - mn0); s0 += sc[in][0];
                sc[in][1] = ex2(sc[in][1] - mn0); s0 += sc[in][1];
                sc[in][2] = ex2(sc[in][2] - mn1); s1 += sc[in][2];
                sc[in][3] = ex2(sc[in][3] - mn1); s1 += sc[in][3];
            }
            s0 += __shfl_xor_sync(0xffffffffu, s0, 1);
            s0 += __shfl_xor_sync(0xffffffffu, s0, 2);
            s1 += __shfl_xor_sync(0xffffffffu, s1, 1);
            s1 += __shfl_xor_sync(0xffffffffu, s1, 2);
            l0r = l0r*c0 + s0; l1r = l1r*c1 + s1;
            m0r = mn0; m1r = mn1;

            // skip rescale when max unchanged for the whole warp (c==1 exact)
            if (!__all_sync(0xffffffffu, (c0 == 1.0f) && (c1 == 1.0f))) {
                #pragma unroll
                for (int dn = 0; dn < 8; dn++) {
                    O[dn][0] *= c0; O[dn][1] *= c0;
                    O[dn][2] *= c1; O[dn][3] *= c1;
                }
            }

            // ---- O += P V ----
            #pragma unroll
            for (int u = 0; u < 4; u++) {
                unsigned a0 = packh2(sc[2*u  ][0], sc[2*u  ][1]);
                unsigned a1 = packh2(sc[2*u  ][2], sc[2*u  ][3]);
                unsigned a2 = packh2(sc[2*u+1][0], sc[2*u+1][1]);
                unsigned a3 = packh2(sc[2*u+1][2], sc[2*u+1][3]);
                #pragma unroll
                for (int p = 0; p < 4; p++) {
                    unsigned vb[4];
                    ldsm4(vb, Vsub + (unsigned)(((p*16)*VST + 16*u)*2) + offBV);
                    mma_f16(O[2*p  ], a0, a1, a2, a3, vb[0], vb[1]);
                    mma_f16(O[2*p+1], a0, a1, a2, a3, vb[2], vb[3]);
                }
            }
        }
    }

    // ---- epilogue: normalize, write half to g_y ----
    float i0 = 1.0f / l0r, i1 = 1.0f / l1r;
    int b = bh >> 3, h = bh & 7;
    int r0 = q0 + warp*16 + g;
    #pragma unroll
    for (int dn = 0; dn < 8; dn++) {
        int col = h*64 + dn*8 + tig*2;
        *(unsigned*)&g_y[(b*TSEQ + r0    )*CDIM + col] =
            packh2(O[dn][0]*i0, O[dn][1]*i0);
        *(unsigned*)&g_y[(b*TSEQ + r0 + 8)*CDIM + col] =
            packh2(O[dn][2]*i1, O[dn][3]*i1);
    }
}

// ---------------------------------------------------------------------------
// Inputs: x, weight, state, Wq, bq, Wk, bk, Wv, bv, Wp, bp
// ---------------------------------------------------------------------------
extern "C" void kernel_launch(void* const* d_in, const int* in_sizes, int n_in,
                              void* d_out, int out_size)
{
    (void)in_sizes; (void)n_in; (void)out_size;
    const float* x  = (const float*)d_in[0];
    const float* Wq = (const float*)d_in[3];
    const float* bq = (const float*)d_in[4];
    const float* Wk = (const float*)d_in[5];
    const float* bk = (const float*)d_in[6];
    const float* Wv = (const float*)d_in[7];
    const float* bv = (const float*)d_in[8];
    const float* Wp = (const float*)d_in[9];
    const float* bp = (const float*)d_in[10];
    float* out = (float*)d_out;

    static bool attr_done = false;
    if (!attr_done) {
        cudaFuncSetAttribute(attn_f16,
            cudaFuncAttributeMaxDynamicSharedMemorySize, STAGEH*2*sizeof(__half));
        cudaFuncSetAttribute(gemm_h<true>,
            cudaFuncAttributeMaxDynamicSharedMemorySize, GSTG*3*sizeof(__half));
        cudaFuncSetAttribute(gemm_h<false>,
            cudaFuncAttributeMaxDynamicSharedMemorySize, GSTG*3*sizeof(__half));
        attr_done = true;
    }

    // resolve device-global addresses (host side, graph-safe)
    __half *xh_p, *wh_p;
    cudaGetSymbolAddress((void**)&xh_p, g_xh);
    cudaGetSymbolAddress((void**)&wh_p, g_wh);

    // ---- convert x + weights to half ----
    cvt_f2h<<<MROWS*CDIM/1024, 256>>>(x,  xh_p);
    cvt_f2h<<<CDIM*CDIM/1024, 256>>>(Wq, wh_p);
    cvt_f2h<<<CDIM*CDIM/1024, 256>>>(Wk, wh_p + CDIM*CDIM);
    cvt_f2h<<<CDIM*CDIM/1024, 256>>>(Wv, wh_p + 2*CDIM*CDIM);
    cvt_f2h<<<CDIM*CDIM/1024, 256>>>(Wp, wh_p + 3*CDIM*CDIM);

    dim3 gqkv(CDIM/64, MROWS/128, 3);      // (8, 64, 3)
    gemm_h<true><<<gqkv, 256, GSTG*3*sizeof(__half)>>>(bq, bk, bv, nullptr);

    dim3 ga(TSEQ/128, BBATCH*NHEAD);       // (32, 16)
    attn_f16<<<ga, 256, STAGEH*2*sizeof(__half)>>>();

    dim3 gp(CDIM/64, MROWS/128);           // (8, 64)
    gemm_h<false><<<gp, 256, GSTG*3*sizeof(__half)>>>(bp, nullptr, nullptr, out);
}

// round 15
// speedup vs baseline: 6.6492x; 1.0438x over previous
#include <cuda_runtime.h>
#include <cuda_fp16.h>
#include <cstdint>

#define BBATCH 2
#define TSEQ   4096
#define CDIM   512
#define NHEAD  8
#define HDIM   64
#define MROWS  (BBATCH*TSEQ)

// Q scale: 1/sqrt(64) * log2(e)  (softmax in exp2 domain)
#define QSCALE 0.18033688011112042f

// Internal scratch (device globals: allocation-free rule). All half.
__device__ __half g_xh[MROWS*CDIM];              // x converted to half
__device__ __half g_wh[4*CDIM*CDIM];             // Wq,Wk,Wv,Wp in half
__device__ __half g_q[BBATCH*NHEAD*TSEQ*HDIM];   // [b,h,t,d], pre-scaled
__device__ __half g_k[BBATCH*NHEAD*TSEQ*HDIM];   // [b,h,t,d]
__device__ __half g_v[BBATCH*NHEAD*HDIM*TSEQ];   // [b,h,d,t]  (transposed!)
__device__ __half g_y[BBATCH*TSEQ*CDIM];         // attention out, half

__device__ __forceinline__ float ex2(float x){
    float r; asm("ex2.approx.f32 %0, %1;" : "=f"(r) : "f"(x)); return r;
}
__device__ __forceinline__ unsigned packh2(float a, float b){
    __half2 h = __floats2half2_rn(a, b); return *(unsigned*)&h;
}
__device__ __forceinline__ void mma_f16(float c[4],
    unsigned a0, unsigned a1, unsigned a2, unsigned a3,
    unsigned b0, unsigned b1)
{
    asm volatile(
        "mma.sync.aligned.m16n8k16.row.col.f32.f16.f16.f32 "
        "{%0,%1,%2,%3}, {%4,%5,%6,%7}, {%8,%9}, {%0,%1,%2,%3};"
        : "+f"(c[0]), "+f"(c[1]), "+f"(c[2]), "+f"(c[3])
        : "r"(a0), "r"(a1), "r"(a2), "r"(a3), "r"(b0), "r"(b1));
}
__device__ __forceinline__ void ldsm4(unsigned r[4], unsigned addr){
    asm volatile("ldmatrix.sync.aligned.m8n8.x4.shared.b16 {%0,%1,%2,%3}, [%4];"
        : "=r"(r[0]), "=r"(r[1]), "=r"(r[2]), "=r"(r[3]) : "r"(addr));
}
__device__ __forceinline__ void cpa16(void* dst, const void* src){
    unsigned d = (unsigned)__cvta_generic_to_shared(dst);
    asm volatile("cp.async.ca.shared.global [%0], [%1], 16;\n" :: "r"(d), "l"(src));
}
#define CP_COMMIT()  asm volatile("cp.async.commit_group;\n")
#define CP_WAIT(N)   asm volatile("cp.async.wait_group %0;\n" :: "n"(N))

// Per-lane ldmatrix source offsets.
__device__ __forceinline__ int lda_row(int lane){ return ((lane >> 3) & 1) * 8 + (lane & 7); }
__device__ __forceinline__ int lda_col(int lane){ return (lane >> 4) * 8; }
__device__ __forceinline__ int ldb_row(int lane){ return (lane >> 4) * 8 + (lane & 7); }
__device__ __forceinline__ int ldb_col(int lane){ return ((lane >> 3) & 1) * 8; }

// ---------------------------------------------------------------------------
// Fused fp32 -> fp16 conversion: x (4096 blocks) + 4 weights (256 blocks each)
// ---------------------------------------------------------------------------
__global__ __launch_bounds__(256,8) void cvt_all(
    const float* __restrict__ x,
    const float* __restrict__ Wq, const float* __restrict__ Wk,
    const float* __restrict__ Wv, const float* __restrict__ Wp,
    __half* __restrict__ xh, __half* __restrict__ wh)
{
    const float* src; __half* dst; int base;
    int bx = blockIdx.x;
    if (bx < 4096) { src = x; dst = xh; base = bx; }
    else {
        int seg = (bx - 4096) >> 8;            // 0..3
        src = (seg == 0) ? Wq : (seg == 1) ? Wk : (seg == 2) ? Wv : Wp;
        dst = wh + seg*(CDIM*CDIM);
        base = (bx - 4096) & 255;
    }
    int i = (base*256 + threadIdx.x) * 4;
    float4 v = *(const float4*)(src + i);
    *(uint2*)(dst + i) = make_uint2(packh2(v.x, v.y), packh2(v.z, v.w));
}

// ---------------------------------------------------------------------------
// GEMM core: out = A @ W^T + bias.  A,W half in gmem.
// Block tile 256x64, BK=64, 256 thr = 8 warps (4M x 2N), warp 64x32.
// 2-stage cp.async pipeline, ONE barrier per iteration, LDSM fragments.
// Smem stride 72 halves (LDSM row bank 4r mod 32: conflict-free).
// ---------------------------------------------------------------------------
#define GAST 72
#define GASTG (256*GAST)             // A tile halves = 18432
#define GBSTG (64*GAST)              // B tile halves = 4608
#define GSTG  (GASTG + GBSTG)        // 23040 halves = 46080 B / stage

template<bool QKV>
__global__ __launch_bounds__(256,2) void gemm_h(
    const float* __restrict__ bias_q, const float* __restrict__ bias_k,
    const float* __restrict__ bias_v, float* __restrict__ outp)
{
    extern __shared__ __half gs[];   // 2 stages

    const int z = QKV ? blockIdx.z : 3;
    const __half* __restrict__ A = QKV ? g_xh : g_y;
    const __half* __restrict__ W = g_wh + z*(CDIM*CDIM);
    const float* __restrict__ bias =
        (z == 0) ? bias_q : (z == 1) ? bias_k : (z == 2) ? bias_v : bias_q;

    const int tid = threadIdx.x, lane = tid & 31, warp = tid >> 5;
    const int wm = warp >> 1, wn = warp & 1;
    const int g = lane >> 2, tig = lane & 3;
    const int m0 = blockIdx.y * 256, n0 = blockIdx.x * 64;

    const unsigned smsh = (unsigned)__cvta_generic_to_shared(gs);
    const unsigned offA = (unsigned)((lda_row(lane)*GAST + lda_col(lane)) * 2);
    const unsigned offB = (unsigned)((ldb_row(lane)*GAST + ldb_col(lane)) * 2);

    auto copy_stage = [&](int it, int s) {
        const int k0 = it << 6;
        __half* Ad = gs + s*GSTG;
        __half* Bd = Ad + GASTG;
        #pragma unroll
        for (int l = 0; l < 8; l++) {
            int id = tid + l*256; int row = id >> 3, c = id & 7;
            cpa16(Ad + row*GAST + c*8, A + (m0 + row)*CDIM + k0 + c*8);
        }
        #pragma unroll
        for (int l = 0; l < 2; l++) {
            int id = tid + l*256; int row = id >> 3, c = id & 7;
            cpa16(Bd + row*GAST + c*8, W + (n0 + row)*CDIM + k0 + c*8);
        }
        CP_COMMIT();
    };

    copy_stage(0, 0);

    float acc[4][4][4] = {};

    for (int it = 0; it < 8; it++) {
        const int s = it & 1;
        CP_WAIT(0);
        __syncthreads();                       // stage s ready; s^1 reads done
        if (it + 1 < 8) copy_stage(it + 1, s ^ 1);

        const unsigned Ab = smsh + (unsigned)(s*GSTG*2);
        const unsigned Bb = Ab + (unsigned)(GASTG*2);

        #pragma unroll
        for (int u = 0; u < 4; u++) {
            unsigned a[4][4], b[2][4];
            #pragma unroll
            for (int mt = 0; mt < 4; mt++)
                ldsm4(a[mt], Ab + (unsigned)(((wm*64 + mt*16)*GAST + 16*u)*2) + offA);
            ldsm4(b[0], Bb + (unsigned)(((wn*32      )*GAST + 16*u)*2) + offB);
            ldsm4(b[1], Bb + (unsigned)(((wn*32 + 16 )*GAST + 16*u)*2) + offB);
            #pragma unroll
            for (int mt = 0; mt < 4; mt++) {
                #pragma unroll
                for (int nt = 0; nt < 4; nt++) {
                    unsigned b0 = b[nt>>1][(nt&1)*2], b1 = b[nt>>1][(nt&1)*2+1];
                    mma_f16(acc[mt][nt], a[mt][0], a[mt][1], a[mt][2], a[mt][3],
                            b0, b1);
                }
            }
        }
    }

    #pragma unroll
    for (int mt = 0; mt < 4; mt++) {
        #pragma unroll
        for (int r = 0; r < 2; r++) {
            int row = m0 + wm*64 + mt*16 + g + r*8;
            #pragma unroll
            for (int nt = 0; nt < 4; nt++) {
                int col = n0 + wn*32 + nt*8 + tig*2;
                float2 bv = *(const float2*)(bias + col);
                float vx = acc[mt][nt][r*2+0] + bv.x;
                float vy = acc[mt][nt][r*2+1] + bv.y;
                if (!QKV) {
                    *(float2*)(outp + row*CDIM + col) = make_float2(vx, vy);
                } else {
                    int b = row >> 12, t = row & 4095, h = col >> 6, d = col & 63;
                    if (z == 0) {
                        vx *= QSCALE; vy *= QSCALE;
                        *(unsigned*)&g_q[(((b*NHEAD + h)*TSEQ + t) << 6) + d] =
                            packh2(vx, vy);
                    } else if (z == 1) {
                        *(unsigned*)&g_k[(((b*NHEAD + h)*TSEQ + t) << 6) + d] =
                            packh2(vx, vy);
                    } else {
                        __half* vp = g_v + (((b*NHEAD + h)*HDIM + d)*TSEQ) + t;
                        vp[0]    = __float2half_rn(vx);
                        vp[TSEQ] = __float2half_rn(vy);
                    }
                }
            }
        }
    }
}

// ---------------------------------------------------------------------------
// Flash attention, fp16 mma.  Block = 128 q-rows x (b,h).  8 warps, 2 CTAs/SM.
// KT=128 stages (two 64-key sub-tiles), single __syncthreads per stage.
// K [key][d] stride 72; V [d][key] stride 136 (both conflict-free for LDSM).
// cp.async double buffering; copy issued AFTER the stage barrier.
// l-sum kept per-lane; reduced once in the epilogue (c uniform across group).
// ---------------------------------------------------------------------------
#define AST    72
#define VST    136
#define KTILEH (128*AST)              // 9216 halves
#define STAGEH (KTILEH + 64*VST)      // 17920 halves = 35840 B

__global__ __launch_bounds__(256,2) void attn_f16()
{
    extern __shared__ __half sm[];   // 2 stages = 71680 B

    const int tid = threadIdx.x, lane = tid & 31, warp = tid >> 5;
    const int g = lane >> 2, tig = lane & 3;
    const int qi = (TSEQ/128 - 1) - blockIdx.x;     // big tiles first
    const int bh = blockIdx.y;
    const int q0 = qi * 128;
    const __half* __restrict__ Qp = g_q + bh*(TSEQ*HDIM);
    const __half* __restrict__ Kp = g_k + bh*(TSEQ*HDIM);
    const __half* __restrict__ Vp = g_v + bh*(HDIM*TSEQ);

    const unsigned smsh = (unsigned)__cvta_generic_to_shared(sm);
    const unsigned offA = (unsigned)((lda_row(lane)*AST + lda_col(lane)) * 2);
    const unsigned offBK = (unsigned)((ldb_row(lane)*AST + ldb_col(lane)) * 2);
    const unsigned offBV = (unsigned)((ldb_row(lane)*VST + ldb_col(lane)) * 2);

    // ---- stage Q into stage-0 K region, load A-frags ----
    #pragma unroll
    for (int l = 0; l < 4; l++) {
        int id = tid + l*256; int row = id >> 3, c = id & 7;
        cpa16(sm + row*AST + c*8, Qp + ((q0 + row) << 6) + c*8);
    }
    CP_COMMIT();
    CP_WAIT(0);
    __syncthreads();

    unsigned qa[4][4];
    #pragma unroll
    for (int u = 0; u < 4; u++)
        ldsm4(qa[u], smsh + (unsigned)(((warp*16)*AST + 16*u)*2) + offA);
    __syncthreads();   // all warps done with Q before stage-0 overwrite

    const int nst  = qi + 1;          // 128-key stages
    const int nk64 = 2*qi + 2;        // 64-key sub-tiles

    auto copy_stage = [&](int st, int s) {
        const int k0 = st << 7;
        __half* Kd = sm + s*STAGEH;
        __half* Vd = Kd + KTILEH;
        #pragma unroll
        for (int l = 0; l < 4; l++) {
            int id = tid + l*256; int row = id >> 3, c = id & 7;
            cpa16(Kd + row*AST + c*8, Kp + ((k0 + row) << 6) + c*8);
        }
        #pragma unroll
        for (int l = 0; l < 4; l++) {
            int id = tid + l*256; int row = id >> 4, c = id & 15;
            cpa16(Vd + row*VST + c*8, Vp + row*TSEQ + k0 + c*8);
        }
        CP_COMMIT();
    };

    copy_stage(0, 0);

    float m0r = -1e30f, m1r = -1e30f, l0r = 0.f, l1r = 0.f;
    float O[8][4] = {};

    for (int st = 0; st < nst; st++) {
        const int s = st & 1;
        CP_WAIT(0);
        __syncthreads();              // stage s ready; stage s^1 reads done
        if (st + 1 < nst) copy_stage(st + 1, s ^ 1);

        const unsigned Kb = smsh + (unsigned)(s*STAGEH*2);
        const unsigned Vb = Kb + (unsigned)(KTILEH*2);

        #pragma unroll
        for (int sub = 0; sub < 2; sub++) {
            const int kk = 2*st + sub;            // 64-key tile index
            const unsigned Ksub = Kb + (unsigned)(sub*64*AST*2);
            const unsigned Vsub = Vb + (unsigned)(sub*64*2);

            // ---- S = Q K^T ----
            float sc[8][4] = {};
            #pragma unroll
            for (int u = 0; u < 4; u++) {
                #pragma unroll
                for (int p = 0; p < 4; p++) {
                    unsigned kb[4];
                    ldsm4(kb, Ksub + (unsigned)(((p*16)*AST + 16*u)*2) + offBK);
                    mma_f16(sc[2*p  ], qa[u][0], qa[u][1], qa[u][2], qa[u][3],
                            kb[0], kb[1]);
                    mma_f16(sc[2*p+1], qa[u][0], qa[u][1], qa[u][2], qa[u][3],
                            kb[2], kb[3]);
                }
            }

            // ---- causal mask (last two 64-key tiles only) ----
            if (kk >= nk64 - 2) {
                int rbase = q0 + warp*16 + g;
                #pragma unroll
                for (int in = 0; in < 8; in++) {
                    int cb = (kk << 6) + in*8 + tig*2;
                    if (cb     > rbase)     sc[in][0] = -1e30f;
                    if (cb + 1 > rbase)     sc[in][1] = -1e30f;
                    if (cb     > rbase + 8) sc[in][2] = -1e30f;
                    if (cb + 1 > rbase + 8) sc[in][3] = -1e30f;
                }
            }

            // ---- online softmax (exp2 domain); l kept per-lane ----
            float mx0 = -1e30f, mx1 = -1e30f;
            #pragma unroll
            for (int in = 0; in < 8; in++) {
                mx0 = fmaxf(mx0, fmaxf(sc[in][0], sc[in][1]));
                mx1 = fmaxf(mx1, fmaxf(sc[in][2], sc[in][3]));
            }
            mx0 = fmaxf(mx0, __shfl_xor_sync(0xffffffffu, mx0, 1));
            mx0 = fmaxf(mx0, __shfl_xor_sync(0xffffffffu, mx0, 2));
            mx1 = fmaxf(mx1, __shfl_xor_sync(0xffffffffu, mx1, 1));
            mx1 = fmaxf(mx1, __shfl_xor_sync(0xffffffffu, mx1, 2));
            float mn0 = fmaxf(m0r, mx0), mn1 = fmaxf(m1r, mx1);
            float c0 = ex2(m0r - mn0), c1 = ex2(m1r - mn1);
            float s0 = 0.f, s1 = 0.f;
            #pragma unroll
            for (int in = 0; in < 8; in++) {
                sc[in][0] = ex2(sc[in][0] - mn0); s0 += sc[in][0];
                sc[in][1] = ex2(sc[in][1] - mn0); s0 += sc[in][1];
                sc[in][2] = ex2(sc[in][2] - mn1); s1 += sc[in][2];
                sc[in][3] = ex2(sc[in][3] - mn1); s1 += sc[in][3];
            }
            l0r = l0r*c0 + s0; l1r = l1r*c1 + s1;   // per-lane partial
            m0r = mn0; m1r = mn1;

            // skip rescale when max unchanged for the whole warp (c==1 exact)
            if (!__all_sync(0xffffffffu, (c0 == 1.0f) && (c1 == 1.0f))) {
                #pragma unroll
                for (int dn = 0; dn < 8; dn++) {
                    O[dn][0] *= c0; O[dn][1] *= c0;
                    O[dn][2] *= c1; O[dn][3] *= c1;
                }
            }

            // ---- O += P V ----
            #pragma unroll
            for (int u = 0; u < 4; u++) {
                unsigned a0 = packh2(sc[2*u  ][0], sc[2*u  ][1]);
                unsigned a1 = packh2(sc[2*u  ][2], sc[2*u  ][3]);
                unsigned a2 = packh2(sc[2*u+1][0], sc[2*u+1][1]);
                unsigned a3 = packh2(sc[2*u+1][2], sc[2*u+1][3]);
                #pragma unroll
                for (int p = 0; p < 4; p++) {
                    unsigned vb[4];
                    ldsm4(vb, Vsub + (unsigned)(((p*16)*VST + 16*u)*2) + offBV);
                    mma_f16(O[2*p  ], a0, a1, a2, a3, vb[0], vb[1]);
                    mma_f16(O[2*p+1], a0, a1, a2, a3, vb[2], vb[3]);
                }
            }
        }
    }

    // ---- epilogue: reduce l across the tig group, normalize, write half ----
    l0r += __shfl_xor_sync(0xffffffffu, l0r, 1);
    l0r += __shfl_xor_sync(0xffffffffu, l0r, 2);
    l1r += __shfl_xor_sync(0xffffffffu, l1r, 1);
    l1r += __shfl_xor_sync(0xffffffffu, l1r, 2);
    float i0 = 1.0f / l0r, i1 = 1.0f / l1r;
    int b = bh >> 3, h = bh & 7;
    int r0 = q0 + warp*16 + g;
    #pragma unroll
    for (int dn = 0; dn < 8; dn++) {
        int col = h*64 + dn*8 + tig*2;
        *(unsigned*)&g_y[(b*TSEQ + r0    )*CDIM + col] =
            packh2(O[dn][0]*i0, O[dn][1]*i0);
        *(unsigned*)&g_y[(b*TSEQ + r0 + 8)*CDIM + col] =
            packh2(O[dn][2]*i1, O[dn][3]*i1);
    }
}

// ---------------------------------------------------------------------------
// Inputs: x, weight, state, Wq, bq, Wk, bk, Wv, bv, Wp, bp
// ---------------------------------------------------------------------------
extern "C" void kernel_launch(void* const* d_in, const int* in_sizes, int n_in,
                              void* d_out, int out_size)
{
    (void)in_sizes; (void)n_in; (void)out_size;
    const float* x  = (const float*)d_in[0];
    const float* Wq = (const float*)d_in[3];
    const float* bq = (const float*)d_in[4];
    const float* Wk = (const float*)d_in[5];
    const float* bk = (const float*)d_in[6];
    const float* Wv = (const float*)d_in[7];
    const float* bv = (const float*)d_in[8];
    const float* Wp = (const float*)d_in[9];
    const float* bp = (const float*)d_in[10];
    float* out = (float*)d_out;

    static bool attr_done = false;
    if (!attr_done) {
        cudaFuncSetAttribute(attn_f16,
            cudaFuncAttributeMaxDynamicSharedMemorySize, STAGEH*2*sizeof(__half));
        cudaFuncSetAttribute(gemm_h<true>,
            cudaFuncAttributeMaxDynamicSharedMemorySize, GSTG*2*sizeof(__half));
        cudaFuncSetAttribute(gemm_h<false>,
            cudaFuncAttributeMaxDynamicSharedMemorySize, GSTG*2*sizeof(__half));
        attr_done = true;
    }

    __half *xh_p, *wh_p;
    cudaGetSymbolAddress((void**)&xh_p, g_xh);
    cudaGetSymbolAddress((void**)&wh_p, g_wh);

    // ---- fused convert: x + 4 weights ----
    cvt_all<<<4096 + 4*256, 256>>>(x, Wq, Wk, Wv, Wp, xh_p, wh_p);

    dim3 gqkv(CDIM/64, MROWS/256, 3);      // (8, 32, 3)
    gemm_h<true><<<gqkv, 256, GSTG*2*sizeof(__half)>>>(bq, bk, bv, nullptr);

    dim3 ga(TSEQ/128, BBATCH*NHEAD);       // (32, 16)
    attn_f16<<<ga, 256, STAGEH*2*sizeof(__half)>>>();

    dim3 gp(CDIM/64, MROWS/256);           // (8, 32)
    gemm_h<false><<<gp, 256, GSTG*2*sizeof(__half)>>>(bp, nullptr, nullptr, out);
}

// round 16
// speedup vs baseline: 6.8639x; 1.0323x over previous
#include <cuda_runtime.h>
#include <cuda_fp16.h>
#include <cstdint>

#define BBATCH 2
#define TSEQ   4096
#define CDIM   512
#define NHEAD  8
#define HDIM   64
#define MROWS  (BBATCH*TSEQ)

// Q scale: 1/sqrt(64) * log2(e)  (softmax in exp2 domain)
#define QSCALE 0.18033688011112042f

// Internal scratch (device globals: allocation-free rule). All half.
__device__ __half g_xh[MROWS*CDIM];              // x converted to half
__device__ __half g_wh[4*CDIM*CDIM];             // Wq,Wk,Wv,Wp in half
__device__ __half g_q[BBATCH*NHEAD*TSEQ*HDIM];   // [b,h,t,d], pre-scaled
__device__ __half g_k[BBATCH*NHEAD*TSEQ*HDIM];   // [b,h,t,d]
__device__ __half g_v[BBATCH*NHEAD*HDIM*TSEQ];   // [b,h,d,t]  (transposed!)
__device__ __half g_y[BBATCH*TSEQ*CDIM];         // attention out, half

__device__ __forceinline__ float ex2(float x){
    float r; asm("ex2.approx.f32 %0, %1;" : "=f"(r) : "f"(x)); return r;
}
__device__ __forceinline__ unsigned packh2(float a, float b){
    __half2 h = __floats2half2_rn(a, b); return *(unsigned*)&h;
}
// NOTE: not volatile — pure register op, accumulator chain prevents CSE;
// lets NVVM interleave independent mma chains.
__device__ __forceinline__ void mma_f16(float c[4],
    unsigned a0, unsigned a1, unsigned a2, unsigned a3,
    unsigned b0, unsigned b1)
{
    asm("mma.sync.aligned.m16n8k16.row.col.f32.f16.f16.f32 "
        "{%0,%1,%2,%3}, {%4,%5,%6,%7}, {%8,%9}, {%0,%1,%2,%3};"
        : "+f"(c[0]), "+f"(c[1]), "+f"(c[2]), "+f"(c[3])
        : "r"(a0), "r"(a1), "r"(a2), "r"(a3), "r"(b0), "r"(b1));
}
// volatile kept: identical-address LDSM across stage-buffer reuse must NOT CSE.
__device__ __forceinline__ void ldsm4(unsigned r[4], unsigned addr){
    asm volatile("ldmatrix.sync.aligned.m8n8.x4.shared.b16 {%0,%1,%2,%3}, [%4];"
        : "=r"(r[0]), "=r"(r[1]), "=r"(r[2]), "=r"(r[3]) : "r"(addr));
}
__device__ __forceinline__ void cpa16(void* dst, const void* src){
    unsigned d = (unsigned)__cvta_generic_to_shared(dst);
    asm volatile("cp.async.ca.shared.global [%0], [%1], 16;\n" :: "r"(d), "l"(src));
}
#define CP_COMMIT()  asm volatile("cp.async.commit_group;\n")
#define CP_WAIT(N)   asm volatile("cp.async.wait_group %0;\n" :: "n"(N))

// Per-lane ldmatrix source offsets.
__device__ __forceinline__ int lda_row(int lane){ return ((lane >> 3) & 1) * 8 + (lane & 7); }
__device__ __forceinline__ int lda_col(int lane){ return (lane >> 4) * 8; }
__device__ __forceinline__ int ldb_row(int lane){ return (lane >> 4) * 8 + (lane & 7); }
__device__ __forceinline__ int ldb_col(int lane){ return ((lane >> 3) & 1) * 8; }

// ---------------------------------------------------------------------------
// Fused fp32 -> fp16 conversion: x (4096 blocks) + 4 weights (256 blocks each)
// ---------------------------------------------------------------------------
__global__ __launch_bounds__(256,8) void cvt_all(
    const float* __restrict__ x,
    const float* __restrict__ Wq, const float* __restrict__ Wk,
    const float* __restrict__ Wv, const float* __restrict__ Wp,
    __half* __restrict__ xh, __half* __restrict__ wh)
{
    const float* src; __half* dst; int base;
    int bx = blockIdx.x;
    if (bx < 4096) { src = x; dst = xh; base = bx; }
    else {
        int seg = (bx - 4096) >> 8;            // 0..3
        src = (seg == 0) ? Wq : (seg == 1) ? Wk : (seg == 2) ? Wv : Wp;
        dst = wh + seg*(CDIM*CDIM);
        base = (bx - 4096) & 255;
    }
    int i = (base*256 + threadIdx.x) * 4;
    float4 v = *(const float4*)(src + i);
    *(uint2*)(dst + i) = make_uint2(packh2(v.x, v.y), packh2(v.z, v.w));
}

// ---------------------------------------------------------------------------
// GEMM core: out = A @ W^T + bias.  A,W half in gmem.
// Block tile 256x64, BK=64, 256 thr = 8 warps (4M x 2N), warp 64x32.
// 2-stage cp.async pipeline, ONE barrier per iteration, LDSM fragments.
// ---------------------------------------------------------------------------
#define GAST 72
#define GASTG (256*GAST)             // A tile halves = 18432
#define GBSTG (64*GAST)              // B tile halves = 4608
#define GSTG  (GASTG + GBSTG)        // 23040 halves = 46080 B / stage

template<bool QKV>
__global__ __launch_bounds__(256,2) void gemm_h(
    const float* __restrict__ bias_q, const float* __restrict__ bias_k,
    const float* __restrict__ bias_v, float* __restrict__ outp)
{
    extern __shared__ __half gs[];   // 2 stages

    const int z = QKV ? blockIdx.z : 3;
    const __half* __restrict__ A = QKV ? g_xh : g_y;
    const __half* __restrict__ W = g_wh + z*(CDIM*CDIM);
    const float* __restrict__ bias =
        (z == 0) ? bias_q : (z == 1) ? bias_k : (z == 2) ? bias_v : bias_q;

    const int tid = threadIdx.x, lane = tid & 31, warp = tid >> 5;
    const int wm = warp >> 1, wn = warp & 1;
    const int g = lane >> 2, tig = lane & 3;
    const int m0 = blockIdx.y * 256, n0 = blockIdx.x * 64;

    const unsigned smsh = (unsigned)__cvta_generic_to_shared(gs);
    const unsigned offA = (unsigned)((lda_row(lane)*GAST + lda_col(lane)) * 2);
    const unsigned offB = (unsigned)((ldb_row(lane)*GAST + ldb_col(lane)) * 2);

    auto copy_stage = [&](int it, int s) {
        const int k0 = it << 6;
        __half* Ad = gs + s*GSTG;
        __half* Bd = Ad + GASTG;
        #pragma unroll
        for (int l = 0; l < 8; l++) {
            int id = tid + l*256; int row = id >> 3, c = id & 7;
            cpa16(Ad + row*GAST + c*8, A + (m0 + row)*CDIM + k0 + c*8);
        }
        #pragma unroll
        for (int l = 0; l < 2; l++) {
            int id = tid + l*256; int row = id >> 3, c = id & 7;
            cpa16(Bd + row*GAST + c*8, W + (n0 + row)*CDIM + k0 + c*8);
        }
        CP_COMMIT();
    };

    copy_stage(0, 0);

    float acc[4][4][4] = {};

    for (int it = 0; it < 8; it++) {
        const int s = it & 1;
        CP_WAIT(0);
        __syncthreads();                       // stage s ready; s^1 reads done
        if (it + 1 < 8) copy_stage(it + 1, s ^ 1);

        const unsigned Ab = smsh + (unsigned)(s*GSTG*2);
        const unsigned Bb = Ab + (unsigned)(GASTG*2);

        #pragma unroll
        for (int u = 0; u < 4; u++) {
            unsigned a[4][4], b[2][4];
            #pragma unroll
            for (int mt = 0; mt < 4; mt++)
                ldsm4(a[mt], Ab + (unsigned)(((wm*64 + mt*16)*GAST + 16*u)*2) + offA);
            ldsm4(b[0], Bb + (unsigned)(((wn*32      )*GAST + 16*u)*2) + offB);
            ldsm4(b[1], Bb + (unsigned)(((wn*32 + 16 )*GAST + 16*u)*2) + offB);
            #pragma unroll
            for (int mt = 0; mt < 4; mt++) {
                #pragma unroll
                for (int nt = 0; nt < 4; nt++) {
                    unsigned b0 = b[nt>>1][(nt&1)*2], b1 = b[nt>>1][(nt&1)*2+1];
                    mma_f16(acc[mt][nt], a[mt][0], a[mt][1], a[mt][2], a[mt][3],
                            b0, b1);
                }
            }
        }
    }

    #pragma unroll
    for (int mt = 0; mt < 4; mt++) {
        #pragma unroll
        for (int r = 0; r < 2; r++) {
            int row = m0 + wm*64 + mt*16 + g + r*8;
            #pragma unroll
            for (int nt = 0; nt < 4; nt++) {
                int col = n0 + wn*32 + nt*8 + tig*2;
                float2 bv = *(const float2*)(bias + col);
                float vx = acc[mt][nt][r*2+0] + bv.x;
                float vy = acc[mt][nt][r*2+1] + bv.y;
                if (!QKV) {
                    *(float2*)(outp + row*CDIM + col) = make_float2(vx, vy);
                } else {
                    int b = row >> 12, t = row & 4095, h = col >> 6, d = col & 63;
                    if (z == 0) {
                        vx *= QSCALE; vy *= QSCALE;
                        *(unsigned*)&g_q[(((b*NHEAD + h)*TSEQ + t) << 6) + d] =
                            packh2(vx, vy);
                    } else if (z == 1) {
                        *(unsigned*)&g_k[(((b*NHEAD + h)*TSEQ + t) << 6) + d] =
                            packh2(vx, vy);
                    } else {
                        __half* vp = g_v + (((b*NHEAD + h)*HDIM + d)*TSEQ) + t;
                        vp[0]    = __float2half_rn(vx);
                        vp[TSEQ] = __float2half_rn(vy);
                    }
                }
            }
        }
    }
}

// ---------------------------------------------------------------------------
// Flash attention, fp16 mma.  Block = 128 q-rows x (b,h).  8 warps, 2 CTAs/SM.
// KT=128 stages; single barrier per stage; cp.async double buffering.
// Double-buffered LDSM fragment prefetch in S and PV phases.
// Warps 0-3 skip the final (fully-masked for them) diagonal subtile.
// ---------------------------------------------------------------------------
#define AST    72
#define VST    136
#define KTILEH (128*AST)              // 9216 halves
#define STAGEH (KTILEH + 64*VST)      // 17920 halves = 35840 B

__global__ __launch_bounds__(256,2) void attn_f16()
{
    extern __shared__ __half sm[];   // 2 stages = 71680 B

    const int tid = threadIdx.x, lane = tid & 31, warp = tid >> 5;
    const int g = lane >> 2, tig = lane & 3;
    const int qi = (TSEQ/128 - 1) - blockIdx.x;     // big tiles first
    const int bh = blockIdx.y;
    const int q0 = qi * 128;
    const __half* __restrict__ Qp = g_q + bh*(TSEQ*HDIM);
    const __half* __restrict__ Kp = g_k + bh*(TSEQ*HDIM);
    const __half* __restrict__ Vp = g_v + bh*(HDIM*TSEQ);

    const unsigned smsh = (unsigned)__cvta_generic_to_shared(sm);
    const unsigned offA = (unsigned)((lda_row(lane)*AST + lda_col(lane)) * 2);
    const unsigned offBK = (unsigned)((ldb_row(lane)*AST + ldb_col(lane)) * 2);
    const unsigned offBV = (unsigned)((ldb_row(lane)*VST + ldb_col(lane)) * 2);

    // ---- stage Q into stage-0 K region, load A-frags ----
    #pragma unroll
    for (int l = 0; l < 4; l++) {
        int id = tid + l*256; int row = id >> 3, c = id & 7;
        cpa16(sm + row*AST + c*8, Qp + ((q0 + row) << 6) + c*8);
    }
    CP_COMMIT();
    CP_WAIT(0);
    __syncthreads();

    unsigned qa[4][4];
    #pragma unroll
    for (int u = 0; u < 4; u++)
        ldsm4(qa[u], smsh + (unsigned)(((warp*16)*AST + 16*u)*2) + offA);
    __syncthreads();   // all warps done with Q before stage-0 overwrite

    const int nst  = qi + 1;          // 128-key stages
    const int nk64 = 2*qi + 2;        // 64-key sub-tiles

    auto copy_stage = [&](int st, int s) {
        const int k0 = st << 7;
        __half* Kd = sm + s*STAGEH;
        __half* Vd = Kd + KTILEH;
        #pragma unroll
        for (int l = 0; l < 4; l++) {
            int id = tid + l*256; int row = id >> 3, c = id & 7;
            cpa16(Kd + row*AST + c*8, Kp + ((k0 + row) << 6) + c*8);
        }
        #pragma unroll
        for (int l = 0; l < 4; l++) {
            int id = tid + l*256; int row = id >> 4, c = id & 15;
            cpa16(Vd + row*VST + c*8, Vp + row*TSEQ + k0 + c*8);
        }
        CP_COMMIT();
    };

    copy_stage(0, 0);

    float m0r = -1e30f, m1r = -1e30f, l0r = 0.f, l1r = 0.f;
    float O[8][4] = {};

    for (int st = 0; st < nst; st++) {
        const int s = st & 1;
        CP_WAIT(0);
        __syncthreads();              // stage s ready; stage s^1 reads done
        if (st + 1 < nst) copy_stage(st + 1, s ^ 1);

        const unsigned Kb = smsh + (unsigned)(s*STAGEH*2);
        const unsigned Vb = Kb + (unsigned)(KTILEH*2);

        #pragma unroll
        for (int sub = 0; sub < 2; sub++) {
            const int kk = 2*st + sub;            // 64-key tile index

            // warps 0-3 are fully masked on the final diagonal subtile:
            // contribution is provably zero (mx=-inf, c=1, P=0) -> skip all.
            if (kk == nk64 - 1 && warp < 4) continue;

            const unsigned Ksub = Kb + (unsigned)(sub*64*AST*2);
            const unsigned Vsub = Vb + (unsigned)(sub*64*2);

            // ---- S = Q K^T  (double-buffered LDSM prefetch) ----
            float sc[8][4] = {};
            {
                unsigned kbA[4], kbB[4];
                ldsm4(kbA, Ksub + offBK);          // i=0: u=0,p=0
                #pragma unroll
                for (int i = 0; i < 16; i++) {
                    int u = i >> 2, p = i & 3;
                    unsigned* cur = (i & 1) ? kbB : kbA;
                    unsigned* nxt = (i & 1) ? kbA : kbB;
                    if (i < 15) {
                        int u2 = (i+1) >> 2, p2 = (i+1) & 3;
                        ldsm4(nxt, Ksub + (unsigned)(((p2*16)*AST + 16*u2)*2) + offBK);
                    }
                    mma_f16(sc[2*p  ], qa[u][0], qa[u][1], qa[u][2], qa[u][3],
                            cur[0], cur[1]);
                    mma_f16(sc[2*p+1], qa[u][0], qa[u][1], qa[u][2], qa[u][3],
                            cur[2], cur[3]);
                }
            }

            // ---- causal mask (last two 64-key tiles only) ----
            if (kk >= nk64 - 2) {
                int rbase = q0 + warp*16 + g;
                #pragma unroll
                for (int in = 0; in < 8; in++) {
                    int cb = (kk << 6) + in*8 + tig*2;
                    if (cb     > rbase)     sc[in][0] = -1e30f;
                    if (cb + 1 > rbase)     sc[in][1] = -1e30f;
                    if (cb     > rbase + 8) sc[in][2] = -1e30f;
                    if (cb + 1 > rbase + 8) sc[in][3] = -1e30f;
                }
            }

            // ---- online softmax (exp2 domain); l kept per-lane ----
            float mx0 = -1e30f, mx1 = -1e30f;
            #pragma unroll
            for (int in = 0; in < 8; in++) {
                mx0 = fmaxf(mx0, fmaxf(sc[in][0], sc[in][1]));
                mx1 = fmaxf(mx1, fmaxf(sc[in][2], sc[in][3]));
            }
            mx0 = fmaxf(mx0, __shfl_xor_sync(0xffffffffu, mx0, 1));
            mx0 = fmaxf(mx0, __shfl_xor_sync(0xffffffffu, mx0, 2));
            mx1 = fmaxf(mx1, __shfl_xor_sync(0xffffffffu, mx1, 1));
            mx1 = fmaxf(mx1, __shfl_xor_sync(0xffffffffu, mx1, 2));
            float mn0 = fmaxf(m0r, mx0), mn1 = fmaxf(m1r, mx1);
            float c0 = ex2(m0r - mn0), c1 = ex2(m1r - mn1);
            float s0 = 0.f, s1 = 0.f;
            #pragma unroll
            for (int in = 0; in < 8; in++) {
                sc[in][0] = ex2(sc[in][0] - mn0); s0 += sc[in][0];
                sc[in][1] = ex2(sc[in][1] - mn0); s0 += sc[in][1];
                sc[in][2] = ex2(sc[in][2] - mn1); s1 += sc[in][2];
                sc[in][3] = ex2(sc[in][3] - mn1); s1 += sc[in][3];
            }
            l0r = l0r*c0 + s0; l1r = l1r*c1 + s1;   // per-lane partial
            m0r = mn0; m1r = mn1;

            // skip rescale when max unchanged for the whole warp (c==1 exact)
            if (!__all_sync(0xffffffffu, (c0 == 1.0f) && (c1 == 1.0f))) {
                #pragma unroll
                for (int dn = 0; dn < 8; dn++) {
                    O[dn][0] *= c0; O[dn][1] *= c0;
                    O[dn][2] *= c1; O[dn][3] *= c1;
                }
            }

            // ---- O += P V  (double-buffered LDSM prefetch) ----
            {
                unsigned vbA[4], vbB[4];
                ldsm4(vbA, Vsub + offBV);          // i=0: u=0,p=0
                unsigned a0 = 0, a1 = 0, a2 = 0, a3 = 0;
                #pragma unroll
                for (int i = 0; i < 16; i++) {
                    int u = i >> 2, p = i & 3;
                    if (p == 0) {
                        a0 = packh2(sc[2*u  ][0], sc[2*u  ][1]);
                        a1 = packh2(sc[2*u  ][2], sc[2*u  ][3]);
                        a2 = packh2(sc[2*u+1][0], sc[2*u+1][1]);
                        a3 = packh2(sc[2*u+1][2], sc[2*u+1][3]);
                    }
                    unsigned* cur = (i & 1) ? vbB : vbA;
                    unsigned* nxt = (i & 1) ? vbA : vbB;
                    if (i < 15) {
                        int u2 = (i+1) >> 2, p2 = (i+1) & 3;
                        ldsm4(nxt, Vsub + (unsigned)(((p2*16)*VST + 16*u2)*2) + offBV);
                    }
                    mma_f16(O[2*p  ], a0, a1, a2, a3, cur[0], cur[1]);
                    mma_f16(O[2*p+1], a0, a1, a2, a3, cur[2], cur[3]);
                }
            }
        }
    }

    // ---- epilogue: reduce l across the tig group, normalize, write half ----
    l0r += __shfl_xor_sync(0xffffffffu, l0r, 1);
    l0r += __shfl_xor_sync(0xffffffffu, l0r, 2);
    l1r += __shfl_xor_sync(0xffffffffu, l1r, 1);
    l1r += __shfl_xor_sync(0xffffffffu, l1r, 2);
    float i0 = 1.0f / l0r, i1 = 1.0f / l1r;
    int b = bh >> 3, h = bh & 7;
    int r0 = q0 + warp*16 + g;
    #pragma unroll
    for (int dn = 0; dn < 8; dn++) {
        int col = h*64 + dn*8 + tig*2;
        *(unsigned*)&g_y[(b*TSEQ + r0    )*CDIM + col] =
            packh2(O[dn][0]*i0, O[dn][1]*i0);
        *(unsigned*)&g_y[(b*TSEQ + r0 + 8)*CDIM + col] =
            packh2(O[dn][2]*i1, O[dn][3]*i1);
    }
}

// ---------------------------------------------------------------------------
// Inputs: x, weight, state, Wq, bq, Wk, bk, Wv, bv, Wp, bp
// ---------------------------------------------------------------------------
extern "C" void kernel_launch(void* const* d_in, const int* in_sizes, int n_in,
                              void* d_out, int out_size)
{
    (void)in_sizes; (void)n_in; (void)out_size;
    const float* x  = (const float*)d_in[0];
    const float* Wq = (const float*)d_in[3];
    const float* bq = (const float*)d_in[4];
    const float* Wk = (const float*)d_in[5];
    const float* bk = (const float*)d_in[6];
    const float* Wv = (const float*)d_in[7];
    const float* bv = (const float*)d_in[8];
    const float* Wp = (const float*)d_in[9];
    const float* bp = (const float*)d_in[10];
    float* out = (float*)d_out;

    static bool attr_done = false;
    if (!attr_done) {
        cudaFuncSetAttribute(attn_f16,
            cudaFuncAttributeMaxDynamicSharedMemorySize, STAGEH*2*sizeof(__half));
        cudaFuncSetAttribute(gemm_h<true>,
            cudaFuncAttributeMaxDynamicSharedMemorySize, GSTG*2*sizeof(__half));
        cudaFuncSetAttribute(gemm_h<false>,
            cudaFuncAttributeMaxDynamicSharedMemorySize, GSTG*2*sizeof(__half));
        attr_done = true;
    }

    __half *xh_p, *wh_p;
    cudaGetSymbolAddress((void**)&xh_p, g_xh);
    cudaGetSymbolAddress((void**)&wh_p, g_wh);

    // ---- fused convert: x + 4 weights ----
    cvt_all<<<4096 + 4*256, 256>>>(x, Wq, Wk, Wv, Wp, xh_p, wh_p);

    dim3 gqkv(CDIM/64, MROWS/256, 3);      // (8, 32, 3)
    gemm_h<true><<<gqkv, 256, GSTG*2*sizeof(__half)>>>(bq, bk, bv, nullptr);

    dim3 ga(TSEQ/128, BBATCH*NHEAD);       // (32, 16)
    attn_f16<<<ga, 256, STAGEH*2*sizeof(__half)>>>();

    dim3 gp(CDIM/64, MROWS/256);           // (8, 32)
    gemm_h<false><<<gp, 256, GSTG*2*sizeof(__half)>>>(bp, nullptr, nullptr, out);
}

// round 17
// speedup vs baseline: 7.1727x; 1.0450x over previous
#include <cuda_runtime.h>
#include <cuda_fp16.h>
#include <cstdint>

#define BBATCH 2
#define TSEQ   4096
#define CDIM   512
#define NHEAD  8
#define HDIM   64
#define MROWS  (BBATCH*TSEQ)

// Q scale: 1/sqrt(64) * log2(e)  (softmax in exp2 domain)
#define QSCALE 0.18033688011112042f
#define ONESH2 0x3C003C00u          // half2(1.0, 1.0)

// Internal scratch (device globals: allocation-free rule). All half.
__device__ __half g_xh[MROWS*CDIM];              // x converted to half
__device__ __half g_wh[4*CDIM*CDIM];             // Wq,Wk,Wv,Wp in half
__device__ __half g_q[BBATCH*NHEAD*TSEQ*HDIM];   // [b,h,t,d], pre-scaled
__device__ __half g_k[BBATCH*NHEAD*TSEQ*HDIM];   // [b,h,t,d]
__device__ __half g_v[BBATCH*NHEAD*HDIM*TSEQ];   // [b,h,d,t]  (transposed!)
__device__ __half g_y[BBATCH*TSEQ*CDIM];         // attention out, half

__device__ __forceinline__ float ex2(float x){
    float r; asm("ex2.approx.f32 %0, %1;" : "=f"(r) : "f"(x)); return r;
}
__device__ __forceinline__ unsigned ex2h2(unsigned x){
    unsigned r; asm("ex2.approx.f16x2 %0, %1;" : "=r"(r) : "r"(x)); return r;
}
__device__ __forceinline__ unsigned packh2(float a, float b){
    __half2 h = __floats2half2_rn(a, b); return *(unsigned*)&h;
}
// not volatile — pure register op; lets NVVM interleave mma chains.
__device__ __forceinline__ void mma_f16(float c[4],
    unsigned a0, unsigned a1, unsigned a2, unsigned a3,
    unsigned b0, unsigned b1)
{
    asm("mma.sync.aligned.m16n8k16.row.col.f32.f16.f16.f32 "
        "{%0,%1,%2,%3}, {%4,%5,%6,%7}, {%8,%9}, {%0,%1,%2,%3};"
        : "+f"(c[0]), "+f"(c[1]), "+f"(c[2]), "+f"(c[3])
        : "r"(a0), "r"(a1), "r"(a2), "r"(a3), "r"(b0), "r"(b1));
}
// volatile kept: identical-address LDSM across stage-buffer reuse must NOT CSE.
__device__ __forceinline__ void ldsm4(unsigned r[4], unsigned addr){
    asm volatile("ldmatrix.sync.aligned.m8n8.x4.shared.b16 {%0,%1,%2,%3}, [%4];"
        : "=r"(r[0]), "=r"(r[1]), "=r"(r[2]), "=r"(r[3]) : "r"(addr));
}
__device__ __forceinline__ void cpa16(void* dst, const void* src){
    unsigned d = (unsigned)__cvta_generic_to_shared(dst);
    asm volatile("cp.async.ca.shared.global [%0], [%1], 16;\n" :: "r"(d), "l"(src));
}
#define CP_COMMIT()  asm volatile("cp.async.commit_group;\n")
#define CP_WAIT(N)   asm volatile("cp.async.wait_group %0;\n" :: "n"(N))

// Per-lane ldmatrix source offsets.
__device__ __forceinline__ int lda_row(int lane){ return ((lane >> 3) & 1) * 8 + (lane & 7); }
__device__ __forceinline__ int lda_col(int lane){ return (lane >> 4) * 8; }
__device__ __forceinline__ int ldb_row(int lane){ return (lane >> 4) * 8 + (lane & 7); }
__device__ __forceinline__ int ldb_col(int lane){ return ((lane >> 3) & 1) * 8; }

// ---------------------------------------------------------------------------
// Fused fp32 -> fp16 conversion: x (4096 blocks) + 4 weights (256 blocks each)
// ---------------------------------------------------------------------------
__global__ __launch_bounds__(256,8) void cvt_all(
    const float* __restrict__ x,
    const float* __restrict__ Wq, const float* __restrict__ Wk,
    const float* __restrict__ Wv, const float* __restrict__ Wp,
    __half* __restrict__ xh, __half* __restrict__ wh)
{
    const float* src; __half* dst; int base;
    int bx = blockIdx.x;
    if (bx < 4096) { src = x; dst = xh; base = bx; }
    else {
        int seg = (bx - 4096) >> 8;            // 0..3
        src = (seg == 0) ? Wq : (seg == 1) ? Wk : (seg == 2) ? Wv : Wp;
        dst = wh + seg*(CDIM*CDIM);
        base = (bx - 4096) & 255;
    }
    int i = (base*256 + threadIdx.x) * 4;
    float4 v = *(const float4*)(src + i);
    *(uint2*)(dst + i) = make_uint2(packh2(v.x, v.y), packh2(v.z, v.w));
}

// ---------------------------------------------------------------------------
// GEMM core: out = A @ W^T + bias.  A,W half in gmem.
// Block tile 256x64, BK=64, 256 thr = 8 warps (4M x 2N), warp 64x32.
// 2-stage cp.async pipeline, ONE barrier per iteration, LDSM fragments.
// ---------------------------------------------------------------------------
#define GAST 72
#define GASTG (256*GAST)             // A tile halves = 18432
#define GBSTG (64*GAST)              // B tile halves = 4608
#define GSTG  (GASTG + GBSTG)        // 23040 halves = 46080 B / stage

template<bool QKV>
__global__ __launch_bounds__(256,2) void gemm_h(
    const float* __restrict__ bias_q, const float* __restrict__ bias_k,
    const float* __restrict__ bias_v, float* __restrict__ outp)
{
    extern __shared__ __half gs[];   // 2 stages

    const int z = QKV ? blockIdx.z : 3;
    const __half* __restrict__ A = QKV ? g_xh : g_y;
    const __half* __restrict__ W = g_wh + z*(CDIM*CDIM);
    const float* __restrict__ bias =
        (z == 0) ? bias_q : (z == 1) ? bias_k : (z == 2) ? bias_v : bias_q;

    const int tid = threadIdx.x, lane = tid & 31, warp = tid >> 5;
    const int wm = warp >> 1, wn = warp & 1;
    const int g = lane >> 2, tig = lane & 3;
    const int m0 = blockIdx.y * 256, n0 = blockIdx.x * 64;

    const unsigned smsh = (unsigned)__cvta_generic_to_shared(gs);
    const unsigned offA = (unsigned)((lda_row(lane)*GAST + lda_col(lane)) * 2);
    const unsigned offB = (unsigned)((ldb_row(lane)*GAST + ldb_col(lane)) * 2);

    auto copy_stage = [&](int it, int s) {
        const int k0 = it << 6;
        __half* Ad = gs + s*GSTG;
        __half* Bd = Ad + GASTG;
        #pragma unroll
        for (int l = 0; l < 8; l++) {
            int id = tid + l*256; int row = id >> 3, c = id & 7;
            cpa16(Ad + row*GAST + c*8, A + (m0 + row)*CDIM + k0 + c*8);
        }
        #pragma unroll
        for (int l = 0; l < 2; l++) {
            int id = tid + l*256; int row = id >> 3, c = id & 7;
            cpa16(Bd + row*GAST + c*8, W + (n0 + row)*CDIM + k0 + c*8);
        }
        CP_COMMIT();
    };

    copy_stage(0, 0);

    float acc[4][4][4] = {};

    for (int it = 0; it < 8; it++) {
        const int s = it & 1;
        CP_WAIT(0);
        __syncthreads();                       // stage s ready; s^1 reads done
        if (it + 1 < 8) copy_stage(it + 1, s ^ 1);

        const unsigned Ab = smsh + (unsigned)(s*GSTG*2);
        const unsigned Bb = Ab + (unsigned)(GASTG*2);

        #pragma unroll
        for (int u = 0; u < 4; u++) {
            unsigned a[4][4], b[2][4];
            #pragma unroll
            for (int mt = 0; mt < 4; mt++)
                ldsm4(a[mt], Ab + (unsigned)(((wm*64 + mt*16)*GAST + 16*u)*2) + offA);
            ldsm4(b[0], Bb + (unsigned)(((wn*32      )*GAST + 16*u)*2) + offB);
            ldsm4(b[1], Bb + (unsigned)(((wn*32 + 16 )*GAST + 16*u)*2) + offB);
            #pragma unroll
            for (int mt = 0; mt < 4; mt++) {
                #pragma unroll
                for (int nt = 0; nt < 4; nt++) {
                    unsigned b0 = b[nt>>1][(nt&1)*2], b1 = b[nt>>1][(nt&1)*2+1];
                    mma_f16(acc[mt][nt], a[mt][0], a[mt][1], a[mt][2], a[mt][3],
                            b0, b1);
                }
            }
        }
    }

    #pragma unroll
    for (int mt = 0; mt < 4; mt++) {
        #pragma unroll
        for (int r = 0; r < 2; r++) {
            int row = m0 + wm*64 + mt*16 + g + r*8;
            #pragma unroll
            for (int nt = 0; nt < 4; nt++) {
                int col = n0 + wn*32 + nt*8 + tig*2;
                float2 bv = *(const float2*)(bias + col);
                float vx = acc[mt][nt][r*2+0] + bv.x;
                float vy = acc[mt][nt][r*2+1] + bv.y;
                if (!QKV) {
                    *(float2*)(outp + row*CDIM + col) = make_float2(vx, vy);
                } else {
                    int b = row >> 12, t = row & 4095, h = col >> 6, d = col & 63;
                    if (z == 0) {
                        vx *= QSCALE; vy *= QSCALE;
                        *(unsigned*)&g_q[(((b*NHEAD + h)*TSEQ + t) << 6) + d] =
                            packh2(vx, vy);
                    } else if (z == 1) {
                        *(unsigned*)&g_k[(((b*NHEAD + h)*TSEQ + t) << 6) + d] =
                            packh2(vx, vy);
                    } else {
                        __half* vp = g_v + (((b*NHEAD + h)*HDIM + d)*TSEQ) + t;
                        vp[0]    = __float2half_rn(vx);
                        vp[TSEQ] = __float2half_rn(vy);
                    }
                }
            }
        }
    }
}

// ---------------------------------------------------------------------------
// Flash attention, fp16 mma.  Block = 128 q-rows x (b,h).  8 warps, 2 CTAs/SM.
// KT=128 stages; single barrier per stage; cp.async double buffering.
// P computed with ex2.approx.f16x2 (halves MUFU); row-sum l accumulated via
// an extra mma against a constant ones B-fragment (rescales exactly like O).
// Warps 0-3 skip the final (fully-masked for them) diagonal subtile.
// ---------------------------------------------------------------------------
#define AST    72
#define VST    136
#define KTILEH (128*AST)              // 9216 halves
#define STAGEH (KTILEH + 64*VST)      // 17920 halves = 35840 B

__global__ __launch_bounds__(256,2) void attn_f16()
{
    extern __shared__ __half sm[];   // 2 stages = 71680 B

    const int tid = threadIdx.x, lane = tid & 31, warp = tid >> 5;
    const int g = lane >> 2, tig = lane & 3;
    const int qi = (TSEQ/128 - 1) - blockIdx.x;     // big tiles first
    const int bh = blockIdx.y;
    const int q0 = qi * 128;
    const __half* __restrict__ Qp = g_q + bh*(TSEQ*HDIM);
    const __half* __restrict__ Kp = g_k + bh*(TSEQ*HDIM);
    const __half* __restrict__ Vp = g_v + bh*(HDIM*TSEQ);

    const unsigned smsh = (unsigned)__cvta_generic_to_shared(sm);
    const unsigned offA = (unsigned)((lda_row(lane)*AST + lda_col(lane)) * 2);
    const unsigned offBK = (unsigned)((ldb_row(lane)*AST + ldb_col(lane)) * 2);
    const unsigned offBV = (unsigned)((ldb_row(lane)*VST + ldb_col(lane)) * 2);

    // ---- stage Q into stage-0 K region, load A-frags ----
    #pragma unroll
    for (int l = 0; l < 4; l++) {
        int id = tid + l*256; int row = id >> 3, c = id & 7;
        cpa16(sm + row*AST + c*8, Qp + ((q0 + row) << 6) + c*8);
    }
    CP_COMMIT();
    CP_WAIT(0);
    __syncthreads();

    unsigned qa[4][4];
    #pragma unroll
    for (int u = 0; u < 4; u++)
        ldsm4(qa[u], smsh + (unsigned)(((warp*16)*AST + 16*u)*2) + offA);
    __syncthreads();   // all warps done with Q before stage-0 overwrite

    const int nst  = qi + 1;          // 128-key stages
    const int nk64 = 2*qi + 2;        // 64-key sub-tiles

    auto copy_stage = [&](int st, int s) {
        const int k0 = st << 7;
        __half* Kd = sm + s*STAGEH;
        __half* Vd = Kd + KTILEH;
        #pragma unroll
        for (int l = 0; l < 4; l++) {
            int id = tid + l*256; int row = id >> 3, c = id & 7;
            cpa16(Kd + row*AST + c*8, Kp + ((k0 + row) << 6) + c*8);
        }
        #pragma unroll
        for (int l = 0; l < 4; l++) {
            int id = tid + l*256; int row = id >> 4, c = id & 15;
            cpa16(Vd + row*VST + c*8, Vp + row*TSEQ + k0 + c*8);
        }
        CP_COMMIT();
    };

    copy_stage(0, 0);

    float m0r = -1e30f, m1r = -1e30f;
    float O[8][4] = {};
    float Ol[4] = {};                 // row-sum accumulator (ones-mma)

    for (int st = 0; st < nst; st++) {
        const int s = st & 1;
        CP_WAIT(0);
        __syncthreads();              // stage s ready; stage s^1 reads done
        if (st + 1 < nst) copy_stage(st + 1, s ^ 1);

        const unsigned Kb = smsh + (unsigned)(s*STAGEH*2);
        const unsigned Vb = Kb + (unsigned)(KTILEH*2);

        #pragma unroll
        for (int sub = 0; sub < 2; sub++) {
            const int kk = 2*st + sub;            // 64-key tile index

            // warps 0-3 are fully masked on the final diagonal subtile:
            // contribution is provably zero -> skip all.
            if (kk == nk64 - 1 && warp < 4) continue;

            const unsigned Ksub = Kb + (unsigned)(sub*64*AST*2);
            const unsigned Vsub = Vb + (unsigned)(sub*64*2);

            // ---- S = Q K^T  (double-buffered LDSM prefetch) ----
            float sc[8][4] = {};
            {
                unsigned kbA[4], kbB[4];
                ldsm4(kbA, Ksub + offBK);          // i=0: u=0,p=0
                #pragma unroll
                for (int i = 0; i < 16; i++) {
                    int u = i >> 2, p = i & 3;
                    unsigned* cur = (i & 1) ? kbB : kbA;
                    unsigned* nxt = (i & 1) ? kbA : kbB;
                    if (i < 15) {
                        int u2 = (i+1) >> 2, p2 = (i+1) & 3;
                        ldsm4(nxt, Ksub + (unsigned)(((p2*16)*AST + 16*u2)*2) + offBK);
                    }
                    mma_f16(sc[2*p  ], qa[u][0], qa[u][1], qa[u][2], qa[u][3],
                            cur[0], cur[1]);
                    mma_f16(sc[2*p+1], qa[u][0], qa[u][1], qa[u][2], qa[u][3],
                            cur[2], cur[3]);
                }
            }

            // ---- causal mask (last two 64-key tiles only) ----
            if (kk >= nk64 - 2) {
                int rbase = q0 + warp*16 + g;
                #pragma unroll
                for (int in = 0; in < 8; in++) {
                    int cb = (kk << 6) + in*8 + tig*2;
                    if (cb     > rbase)     sc[in][0] = -1e30f;
                    if (cb + 1 > rbase)     sc[in][1] = -1e30f;
                    if (cb     > rbase + 8) sc[in][2] = -1e30f;
                    if (cb + 1 > rbase + 8) sc[in][3] = -1e30f;
                }
            }

            // ---- online max (exp2 domain); P deferred to PV phase ----
            float mx0 = -1e30f, mx1 = -1e30f;
            #pragma unroll
            for (int in = 0; in < 8; in++) {
                mx0 = fmaxf(mx0, fmaxf(sc[in][0], sc[in][1]));
                mx1 = fmaxf(mx1, fmaxf(sc[in][2], sc[in][3]));
            }
            mx0 = fmaxf(mx0, __shfl_xor_sync(0xffffffffu, mx0, 1));
            mx0 = fmaxf(mx0, __shfl_xor_sync(0xffffffffu, mx0, 2));
            mx1 = fmaxf(mx1, __shfl_xor_sync(0xffffffffu, mx1, 1));
            mx1 = fmaxf(mx1, __shfl_xor_sync(0xffffffffu, mx1, 2));
            float mn0 = fmaxf(m0r, mx0), mn1 = fmaxf(m1r, mx1);
            float c0 = ex2(m0r - mn0), c1 = ex2(m1r - mn1);
            m0r = mn0; m1r = mn1;

            // rescale O and Ol; skip when max unchanged (c==1 exact)
            if (!__all_sync(0xffffffffu, (c0 == 1.0f) && (c1 == 1.0f))) {
                #pragma unroll
                for (int dn = 0; dn < 8; dn++) {
                    O[dn][0] *= c0; O[dn][1] *= c0;
                    O[dn][2] *= c1; O[dn][3] *= c1;
                }
                Ol[0] *= c0; Ol[1] *= c0; Ol[2] *= c1; Ol[3] *= c1;
            }

            // ---- O += P V  (P = ex2.f16x2(s - mn); l via ones-mma) ----
            {
                unsigned vbA[4], vbB[4];
                ldsm4(vbA, Vsub + offBV);          // i=0: u=0,p=0
                unsigned a0 = 0, a1 = 0, a2 = 0, a3 = 0;
                #pragma unroll
                for (int i = 0; i < 16; i++) {
                    int u = i >> 2, p = i & 3;
                    if (p == 0) {
                        a0 = ex2h2(packh2(sc[2*u  ][0]-mn0, sc[2*u  ][1]-mn0));
                        a1 = ex2h2(packh2(sc[2*u  ][2]-mn1, sc[2*u  ][3]-mn1));
                        a2 = ex2h2(packh2(sc[2*u+1][0]-mn0, sc[2*u+1][1]-mn0));
                        a3 = ex2h2(packh2(sc[2*u+1][2]-mn1, sc[2*u+1][3]-mn1));
                        mma_f16(Ol, a0, a1, a2, a3, ONESH2, ONESH2);
                    }
                    unsigned* cur = (i & 1) ? vbB : vbA;
                    unsigned* nxt = (i & 1) ? vbA : vbB;
                    if (i < 15) {
                        int u2 = (i+1) >> 2, p2 = (i+1) & 3;
                        ldsm4(nxt, Vsub + (unsigned)(((p2*16)*VST + 16*u2)*2) + offBV);
                    }
                    mma_f16(O[2*p  ], a0, a1, a2, a3, cur[0], cur[1]);
                    mma_f16(O[2*p+1], a0, a1, a2, a3, cur[2], cur[3]);
                }
            }
        }
    }

    // ---- epilogue: normalize by Ol (full row sums, no reduction needed) ----
    float i0 = 1.0f / Ol[0], i1 = 1.0f / Ol[2];
    int b = bh >> 3, h = bh & 7;
    int r0 = q0 + warp*16 + g;
    #pragma unroll
    for (int dn = 0; dn < 8; dn++) {
        int col = h*64 + dn*8 + tig*2;
        *(unsigned*)&g_y[(b*TSEQ + r0    )*CDIM + col] =
            packh2(O[dn][0]*i0, O[dn][1]*i0);
        *(unsigned*)&g_y[(b*TSEQ + r0 + 8)*CDIM + col] =
            packh2(O[dn][2]*i1, O[dn][3]*i1);
    }
}

// ---------------------------------------------------------------------------
// Inputs: x, weight, state, Wq, bq, Wk, bk, Wv, bv, Wp, bp
// ---------------------------------------------------------------------------
extern "C" void kernel_launch(void* const* d_in, const int* in_sizes, int n_in,
                              void* d_out, int out_size)
{
    (void)in_sizes; (void)n_in; (void)out_size;
    const float* x  = (const float*)d_in[0];
    const float* Wq = (const float*)d_in[3];
    const float* bq = (const float*)d_in[4];
    const float* Wk = (const float*)d_in[5];
    const float* bk = (const float*)d_in[6];
    const float* Wv = (const float*)d_in[7];
    const float* bv = (const float*)d_in[8];
    const float* Wp = (const float*)d_in[9];
    const float* bp = (const float*)d_in[10];
    float* out = (float*)d_out;

    static bool attr_done = false;
    if (!attr_done) {
        cudaFuncSetAttribute(attn_f16,
            cudaFuncAttributeMaxDynamicSharedMemorySize, STAGEH*2*sizeof(__half));
        cudaFuncSetAttribute(gemm_h<true>,
            cudaFuncAttributeMaxDynamicSharedMemorySize, GSTG*2*sizeof(__half));
        cudaFuncSetAttribute(gemm_h<false>,
            cudaFuncAttributeMaxDynamicSharedMemorySize, GSTG*2*sizeof(__half));
        attr_done = true;
    }

    __half *xh_p, *wh_p;
    cudaGetSymbolAddress((void**)&xh_p, g_xh);
    cudaGetSymbolAddress((void**)&wh_p, g_wh);

    // ---- fused convert: x + 4 weights ----
    cvt_all<<<4096 + 4*256, 256>>>(x, Wq, Wk, Wv, Wp, xh_p, wh_p);

    dim3 gqkv(CDIM/64, MROWS/256, 3);      // (8, 32, 3)
    gemm_h<true><<<gqkv, 256, GSTG*2*sizeof(__half)>>>(bq, bk, bv, nullptr);

    dim3 ga(TSEQ/128, BBATCH*NHEAD);       // (32, 16)
    attn_f16<<<ga, 256, STAGEH*2*sizeof(__half)>>>();

    dim3 gp(CDIM/64, MROWS/256);           // (8, 32)
    gemm_h<false><<<gp, 256, GSTG*2*sizeof(__half)>>>(bp, nullptr, nullptr, out);
}